// round 1
// baseline (speedup 1.0000x reference)
#include <cuda_runtime.h>
#include <cuda_bf16.h>
#include <math.h>

#define BB 2
#define TT 2048
#define CC 1024
#define HH 16
#define DKK 64

// Scratch (no cudaMalloc allowed): QKV in [B,H,T,DK] layout + attention output in [B,T,C]
__device__ float g_q[BB*HH*TT*DKK];
__device__ float g_k[BB*HH*TT*DKK];
__device__ float g_v[BB*HH*TT*DKK];
__device__ float g_att[(size_t)BB*TT*CC];

// ---------------------------------------------------------------------------
// SGEMM NT: C[m][n] = sum_k A[m][k] * B[n][k]   (both row-major, K contiguous)
// 128x128 tile, BK=8, 256 threads, 8x8 per thread.
// mode 0: plain write to Cout[m*N+n]
// mode 1: scatter into g_q/g_k/g_v  ([B,H,T,DK] layout)
// ---------------------------------------------------------------------------
__global__ __launch_bounds__(256) void sgemm_nt(const float* __restrict__ A,
                                                const float* __restrict__ Bw,
                                                float* __restrict__ Cout,
                                                int Kd, int N, int mode)
{
    __shared__ float As[8][128];
    __shared__ float Bs[8][128];
    const int tid = threadIdx.x;
    const int bm = blockIdx.y * 128;
    const int bn = blockIdx.x * 128;
    const int lr = tid >> 1;          // load row 0..127
    const int lk = (tid & 1) * 4;     // load k offset 0 or 4
    const int tx = tid & 15;          // 16 col groups
    const int ty = tid >> 4;          // 16 row groups

    float acc[8][8];
#pragma unroll
    for (int i = 0; i < 8; i++)
#pragma unroll
        for (int j = 0; j < 8; j++) acc[i][j] = 0.f;

    const float* Ap = A  + (size_t)(bm + lr) * Kd + lk;
    const float* Bp = Bw + (size_t)(bn + lr) * Kd + lk;

    for (int kt = 0; kt < Kd; kt += 8) {
        float4 a  = *(const float4*)(Ap + kt);
        float4 bv = *(const float4*)(Bp + kt);
        As[lk + 0][lr] = a.x;  As[lk + 1][lr] = a.y;
        As[lk + 2][lr] = a.z;  As[lk + 3][lr] = a.w;
        Bs[lk + 0][lr] = bv.x; Bs[lk + 1][lr] = bv.y;
        Bs[lk + 2][lr] = bv.z; Bs[lk + 3][lr] = bv.w;
        __syncthreads();
#pragma unroll
        for (int k = 0; k < 8; k++) {
            float ar[8], br[8];
            *(float4*)(ar)     = *(const float4*)&As[k][ty * 8];
            *(float4*)(ar + 4) = *(const float4*)&As[k][ty * 8 + 4];
            *(float4*)(br)     = *(const float4*)&Bs[k][tx * 8];
            *(float4*)(br + 4) = *(const float4*)&Bs[k][tx * 8 + 4];
#pragma unroll
            for (int i = 0; i < 8; i++)
#pragma unroll
                for (int j = 0; j < 8; j++)
                    acc[i][j] = fmaf(ar[i], br[j], acc[i][j]);
        }
        __syncthreads();
    }

    if (mode == 0) {
#pragma unroll
        for (int i = 0; i < 8; i++) {
            int m = bm + ty * 8 + i;
            float* dst = Cout + (size_t)m * N + bn + tx * 8;
            *(float4*)dst       = make_float4(acc[i][0], acc[i][1], acc[i][2], acc[i][3]);
            *(float4*)(dst + 4) = make_float4(acc[i][4], acc[i][5], acc[i][6], acc[i][7]);
        }
    } else {
        // n0..n0+7 never cross a 64-wide head boundary (n0 multiple of 8; 8 | 64)
        int n0    = bn + tx * 8;
        int which = n0 >> 10;
        int rem   = n0 & 1023;
        int h     = rem >> 6;
        int d     = rem & 63;
        float* dstbase = (which == 0) ? g_q : (which == 1) ? g_k : g_v;
#pragma unroll
        for (int i = 0; i < 8; i++) {
            int m = bm + ty * 8 + i;
            int b = m >> 11;       // T = 2048
            int t = m & 2047;
            float* dst = dstbase + (size_t)((b * HH + h) * TT + t) * DKK + d;
            *(float4*)dst       = make_float4(acc[i][0], acc[i][1], acc[i][2], acc[i][3]);
            *(float4*)(dst + 4) = make_float4(acc[i][4], acc[i][5], acc[i][6], acc[i][7]);
        }
    }
}

// ---------------------------------------------------------------------------
// Flash attention fp32, causal. One block per (b, h, 64-query tile).
// 128 threads: tx = tid&7 (keys/cols strided by 8), ty = tid>>3 (4 rows each).
// smem row stride 68 => conflict-free strided K/V reads.
// ---------------------------------------------------------------------------
#define SROW 68
#define ATT_SMEM (4 * 64 * SROW * 4)

__global__ __launch_bounds__(128) void attn_kernel()
{
    extern __shared__ float sm[];
    float* Qs = sm;
    float* Ks = sm + 64 * SROW;
    float* Vs = sm + 2 * 64 * SROW;
    float* Ps = sm + 3 * 64 * SROW;

    const int tid = threadIdx.x;
    const int tx  = tid & 7;
    const int ty  = tid >> 3;
    const int qt  = gridDim.x - 1 - blockIdx.x;   // biggest tiles first
    const int h   = blockIdx.y;
    const int b   = blockIdx.z;
    const int q0  = qt * 64;

    const float* Qg = g_q + (size_t)((b * HH + h) * TT) * DKK;
    const float* Kg = g_k + (size_t)((b * HH + h) * TT) * DKK;
    const float* Vg = g_v + (size_t)((b * HH + h) * TT) * DKK;

    // load Q tile (64 x 64)
#pragma unroll
    for (int it = 0; it < 8; it++) {
        int lin = tid + it * 128;
        int row = lin >> 4;
        int c4  = (lin & 15) * 4;
        *(float4*)&Qs[row * SROW + c4] =
            *(const float4*)&Qg[(size_t)(q0 + row) * DKK + c4];
    }

    float o[4][8];
    float mrow[4], lrow[4];
#pragma unroll
    for (int i = 0; i < 4; i++) {
        mrow[i] = -1e30f; lrow[i] = 0.f;
#pragma unroll
        for (int j = 0; j < 8; j++) o[i][j] = 0.f;
    }

    for (int jt = 0; jt <= qt; jt++) {
        __syncthreads();   // prev PV done (and Q store visible on first iter via 2nd sync)
        int k0 = jt * 64;
#pragma unroll
        for (int it = 0; it < 8; it++) {
            int lin = tid + it * 128;
            int row = lin >> 4;
            int c4  = (lin & 15) * 4;
            *(float4*)&Ks[row * SROW + c4] =
                *(const float4*)&Kg[(size_t)(k0 + row) * DKK + c4];
            *(float4*)&Vs[row * SROW + c4] =
                *(const float4*)&Vg[(size_t)(k0 + row) * DKK + c4];
        }
        __syncthreads();

        // S = Q K^T  (4x8 micro-tile per thread; keys kk = 8j + tx)
        float s[4][8];
#pragma unroll
        for (int i = 0; i < 4; i++)
#pragma unroll
            for (int j = 0; j < 8; j++) s[i][j] = 0.f;

#pragma unroll 8
        for (int d = 0; d < 64; d++) {
            float qv[4], kv[8];
#pragma unroll
            for (int i = 0; i < 4; i++) qv[i] = Qs[(4 * ty + i) * SROW + d];
#pragma unroll
            for (int j = 0; j < 8; j++) kv[j] = Ks[(8 * j + tx) * SROW + d];
#pragma unroll
            for (int i = 0; i < 4; i++)
#pragma unroll
                for (int j = 0; j < 8; j++)
                    s[i][j] = fmaf(qv[i], kv[j], s[i][j]);
        }

        const float sc = 0.125f;   // dk^-0.5
        const bool diag = (jt == qt);
#pragma unroll
        for (int i = 0; i < 4; i++)
#pragma unroll
            for (int j = 0; j < 8; j++) {
                float v = s[i][j] * sc;
                if (diag && (k0 + 8 * j + tx) > (q0 + 4 * ty + i)) v = -1e30f;
                s[i][j] = v;
            }

        // online softmax per row (row shared by 8 lanes: shfl over tx)
        float alpha[4];
#pragma unroll
        for (int i = 0; i < 4; i++) {
            float mloc = s[i][0];
#pragma unroll
            for (int j = 1; j < 8; j++) mloc = fmaxf(mloc, s[i][j]);
            mloc = fmaxf(mloc, __shfl_xor_sync(0xffffffffu, mloc, 1));
            mloc = fmaxf(mloc, __shfl_xor_sync(0xffffffffu, mloc, 2));
            mloc = fmaxf(mloc, __shfl_xor_sync(0xffffffffu, mloc, 4));
            float mnew = fmaxf(mrow[i], mloc);
            alpha[i] = __expf(mrow[i] - mnew);
            float lsum = 0.f;
#pragma unroll
            for (int j = 0; j < 8; j++) {
                s[i][j] = __expf(s[i][j] - mnew);
                lsum += s[i][j];
            }
            lsum += __shfl_xor_sync(0xffffffffu, lsum, 1);
            lsum += __shfl_xor_sync(0xffffffffu, lsum, 2);
            lsum += __shfl_xor_sync(0xffffffffu, lsum, 4);
            lrow[i] = lrow[i] * alpha[i] + lsum;
            mrow[i] = mnew;
        }

#pragma unroll
        for (int i = 0; i < 4; i++)
#pragma unroll
            for (int j = 0; j < 8; j++) o[i][j] *= alpha[i];

        // share P, then O += P V
#pragma unroll
        for (int i = 0; i < 4; i++)
#pragma unroll
            for (int j = 0; j < 8; j++)
                Ps[(4 * ty + i) * SROW + 8 * j + tx] = s[i][j];
        __syncthreads();

#pragma unroll 8
        for (int kk = 0; kk < 64; kk++) {
            float pv[4], vv[8];
#pragma unroll
            for (int i = 0; i < 4; i++) pv[i] = Ps[(4 * ty + i) * SROW + kk];
#pragma unroll
            for (int j = 0; j < 8; j++) vv[j] = Vs[kk * SROW + 8 * j + tx];
#pragma unroll
            for (int i = 0; i < 4; i++)
#pragma unroll
                for (int j = 0; j < 8; j++)
                    o[i][j] = fmaf(pv[i], vv[j], o[i][j]);
        }
    }

    // normalize & write out via smem for coalescing, layout [b, t, h*64 + d]
    __syncthreads();
#pragma unroll
    for (int i = 0; i < 4; i++) {
        float inv = 1.f / lrow[i];
#pragma unroll
        for (int j = 0; j < 8; j++)
            Ps[(4 * ty + i) * SROW + 8 * j + tx] = o[i][j] * inv;
    }
    __syncthreads();
#pragma unroll
    for (int it = 0; it < 8; it++) {
        int lin = tid + it * 128;
        int row = lin >> 4;
        int c4  = (lin & 15) * 4;
        float4 v = *(float4*)&Ps[row * SROW + c4];
        int t = q0 + row;
        *(float4*)&g_att[(size_t)(b * TT + t) * CC + h * DKK + c4] = v;
    }
}

// ---------------------------------------------------------------------------
extern "C" void kernel_launch(void* const* d_in, const int* in_sizes, int n_in,
                              void* d_out, int out_size)
{
    const float* x      = (const float*)d_in[0];   // [2, 2048, 1024]
    const float* w_attn = (const float*)d_in[1];   // [3072, 1024]
    const float* w_proj = (const float*)d_in[2];   // [1024, 1024]
    float* out = (float*)d_out;                    // [2, 2048, 1024]

    // 1) QKV projection, scattered into per-head layout
    {
        dim3 grid(3072 / 128, (BB * TT) / 128);    // (24, 32)
        sgemm_nt<<<grid, 256>>>(x, w_attn, nullptr, CC, 3 * CC, 1);
    }

    // 2) causal flash attention
    {
        cudaFuncSetAttribute(attn_kernel,
                             cudaFuncAttributeMaxDynamicSharedMemorySize, ATT_SMEM);
        dim3 grid(TT / 64, HH, BB);                // (32, 16, 2)
        attn_kernel<<<grid, 128, ATT_SMEM>>>();
    }

    // 3) output projection
    {
        void* attp = nullptr;
        cudaGetSymbolAddress(&attp, g_att);
        dim3 grid(CC / 128, (BB * TT) / 128);      // (8, 32)
        sgemm_nt<<<grid, 256>>>((const float*)attp, w_proj, out, CC, CC, 0);
    }
}

// round 5
// speedup vs baseline: 1.5340x; 1.5340x over previous
#include <cuda_runtime.h>
#include <cuda_bf16.h>
#include <math.h>
#include <cstdint>

#define BB 2
#define TT 2048
#define CC 1024
#define HH 16
#define DKK 64
#define K3 3072   // tripled K: [hi|lo|hi] x [hi|hi|lo]

// fp32 scratch
__device__ float g_q[BB*HH*TT*DKK];
__device__ float g_k[BB*HH*TT*DKK];
__device__ float g_v[BB*HH*TT*DKK];
__device__ float g_att[(size_t)BB*TT*CC];
// bf16 3-block concatenated operands
__device__ __nv_bfloat16 g_xs[(size_t)BB*TT*K3];     // x'      [4096, 3072]
__device__ __nv_bfloat16 g_was[(size_t)3*CC*K3];     // w_attn' [3072, 3072]
__device__ __nv_bfloat16 g_wps[(size_t)CC*K3];       // w_proj' [1024, 3072]
__device__ __nv_bfloat16 g_atts[(size_t)BB*TT*K3];   // att'    [4096, 3072]

__device__ __forceinline__ uint32_t smem_u32(const void* p) {
    uint32_t a;
    asm("{ .reg .u64 t; cvta.to.shared.u64 t, %1; cvt.u32.u64 %0, t; }" : "=r"(a) : "l"(p));
    return a;
}

// ---------------------------------------------------------------------------
// split: fp32 [R,1024] -> bf16 [R,3072].
// mode 0 (A-side): [hi | lo | hi]
// mode 1 (B-side): [hi | hi | lo]
// ---------------------------------------------------------------------------
__global__ __launch_bounds__(256) void split_kernel(const float* __restrict__ in,
                                                    __nv_bfloat16* __restrict__ out,
                                                    int n, int mode)
{
    int i4 = (blockIdx.x * 256 + threadIdx.x) * 4;
    if (i4 >= n) return;
    float4 v = *(const float4*)(in + i4);
    int r = i4 >> 10;
    int c = i4 & 1023;
    __nv_bfloat16 h0 = __float2bfloat16(v.x);
    __nv_bfloat16 h1 = __float2bfloat16(v.y);
    __nv_bfloat16 h2 = __float2bfloat16(v.z);
    __nv_bfloat16 h3 = __float2bfloat16(v.w);
    __nv_bfloat16 l0 = __float2bfloat16(v.x - __bfloat162float(h0));
    __nv_bfloat16 l1 = __float2bfloat16(v.y - __bfloat162float(h1));
    __nv_bfloat16 l2 = __float2bfloat16(v.z - __bfloat162float(h2));
    __nv_bfloat16 l3 = __float2bfloat16(v.w - __bfloat162float(h3));
    __nv_bfloat162 hA = __nv_bfloat162(h0, h1), hB = __nv_bfloat162(h2, h3);
    __nv_bfloat162 lA = __nv_bfloat162(l0, l1), lB = __nv_bfloat162(l2, l3);
    __nv_bfloat162* p0 = (__nv_bfloat162*)(out + (size_t)r * K3 + c);
    __nv_bfloat162* p1 = (__nv_bfloat162*)(out + (size_t)r * K3 + 1024 + c);
    __nv_bfloat162* p2 = (__nv_bfloat162*)(out + (size_t)r * K3 + 2048 + c);
    p0[0] = hA; p0[1] = hB;
    if (mode == 0) { p1[0] = lA; p1[1] = lB; p2[0] = hA; p2[1] = hB; }
    else           { p1[0] = hA; p1[1] = hB; p2[0] = lA; p2[1] = lB; }
}

// ---------------------------------------------------------------------------
// bf16 GEMM NT via mma.sync: C[m][n] = sum_k A'[m][k] * B'[n][k], K = 3072.
// CTA 128x128, BK=32, 8 warps (2x4), warp tile 64x32. cp.async double buffer.
// mode 0: C fp32 row-major ld=1024.  mode 1: scatter fp32 to g_q/g_k/g_v.
// ---------------------------------------------------------------------------
#define RS 40                 // smem row stride (bf16)
#define NCH (K3 / 32)         // 96 chunks

__global__ __launch_bounds__(256) void hgemm_nt(const __nv_bfloat16* __restrict__ A,
                                                const __nv_bfloat16* __restrict__ Bw,
                                                float* __restrict__ Cout,
                                                int mode)
{
    __shared__ __align__(16) __nv_bfloat16 sA[2][128 * RS];
    __shared__ __align__(16) __nv_bfloat16 sB[2][128 * RS];

    const int tid  = threadIdx.x;
    const int lane = tid & 31;
    const int warp = tid >> 5;
    const int wm   = warp & 1;     // 2 m-blocks of 64
    const int wn   = warp >> 1;    // 4 n-blocks of 32
    const int bm   = blockIdx.y * 128;
    const int bn   = blockIdx.x * 128;

    const int r0 = tid >> 2, o0 = tid & 3;
    const int r1 = (tid + 256) >> 2, o1 = (tid + 256) & 3;

    const __nv_bfloat16* Ag = A  + (size_t)(bm) * K3;
    const __nv_bfloat16* Bg = Bw + (size_t)(bn) * K3;

    uint32_t sa0[2], sa1[2], sb0[2], sb1[2];
#pragma unroll
    for (int s = 0; s < 2; s++) {
        sa0[s] = smem_u32(&sA[s][r0 * RS + o0 * 8]);
        sa1[s] = smem_u32(&sA[s][r1 * RS + o1 * 8]);
        sb0[s] = smem_u32(&sB[s][r0 * RS + o0 * 8]);
        sb1[s] = smem_u32(&sB[s][r1 * RS + o1 * 8]);
    }

#define ISSUE_STAGE(buf, ch) do {                                              \
    const __nv_bfloat16* ap0 = Ag + (size_t)r0 * K3 + (ch) * 32 + o0 * 8;      \
    const __nv_bfloat16* ap1 = Ag + (size_t)r1 * K3 + (ch) * 32 + o1 * 8;      \
    const __nv_bfloat16* bp0 = Bg + (size_t)r0 * K3 + (ch) * 32 + o0 * 8;      \
    const __nv_bfloat16* bp1 = Bg + (size_t)r1 * K3 + (ch) * 32 + o1 * 8;      \
    asm volatile("cp.async.cg.shared.global [%0], [%1], 16;" :: "r"(sa0[buf]), "l"(ap0)); \
    asm volatile("cp.async.cg.shared.global [%0], [%1], 16;" :: "r"(sa1[buf]), "l"(ap1)); \
    asm volatile("cp.async.cg.shared.global [%0], [%1], 16;" :: "r"(sb0[buf]), "l"(bp0)); \
    asm volatile("cp.async.cg.shared.global [%0], [%1], 16;" :: "r"(sb1[buf]), "l"(bp1)); \
    asm volatile("cp.async.commit_group;");                                    \
} while (0)

    ISSUE_STAGE(0, 0);
    ISSUE_STAGE(1, 1);

    float acc[4][4][4];
#pragma unroll
    for (int mi = 0; mi < 4; mi++)
#pragma unroll
        for (int ni = 0; ni < 4; ni++)
#pragma unroll
            for (int r = 0; r < 4; r++) acc[mi][ni][r] = 0.f;

    const int l16 = lane & 15;

    for (int c = 0; c < NCH; c++) {
        const int buf = c & 1;
        asm volatile("cp.async.wait_group 1;");
        __syncthreads();

        const __nv_bfloat16* sAb = sA[buf];
        const __nv_bfloat16* sBb = sB[buf];

#pragma unroll
        for (int kk = 0; kk < 2; kk++) {
            uint32_t af[4][4];
            uint32_t bf[4][2];
#pragma unroll
            for (int mi = 0; mi < 4; mi++) {
                uint32_t addr = smem_u32(&sAb[(wm * 64 + mi * 16 + (lane & 15)) * RS
                                              + kk * 16 + (lane >> 4) * 8]);
                asm volatile("ldmatrix.sync.aligned.m8n8.x4.shared.b16 {%0,%1,%2,%3}, [%4];"
                             : "=r"(af[mi][0]), "=r"(af[mi][1]),
                               "=r"(af[mi][2]), "=r"(af[mi][3]) : "r"(addr));
            }
#pragma unroll
            for (int ni = 0; ni < 4; ni++) {
                uint32_t addr = smem_u32(&sBb[(wn * 32 + ni * 8 + (l16 & 7)) * RS
                                              + kk * 16 + (l16 >> 3) * 8]);
                asm volatile("ldmatrix.sync.aligned.m8n8.x2.shared.b16 {%0,%1}, [%2];"
                             : "=r"(bf[ni][0]), "=r"(bf[ni][1]) : "r"(addr));
            }
#pragma unroll
            for (int mi = 0; mi < 4; mi++)
#pragma unroll
                for (int ni = 0; ni < 4; ni++) {
                    asm volatile(
                        "mma.sync.aligned.m16n8k16.row.col.f32.bf16.bf16.f32 "
                        "{%0,%1,%2,%3}, {%4,%5,%6,%7}, {%8,%9}, {%0,%1,%2,%3};"
                        : "+f"(acc[mi][ni][0]), "+f"(acc[mi][ni][1]),
                          "+f"(acc[mi][ni][2]), "+f"(acc[mi][ni][3])
                        : "r"(af[mi][0]), "r"(af[mi][1]), "r"(af[mi][2]), "r"(af[mi][3]),
                          "r"(bf[ni][0]), "r"(bf[ni][1]));
                }
        }

        __syncthreads();
        if (c + 2 < NCH) ISSUE_STAGE(buf, c + 2);
    }

    // epilogue
    const int gid = lane >> 2;
    const int tig = lane & 3;
    if (mode == 0) {
#pragma unroll
        for (int mi = 0; mi < 4; mi++) {
            const int m0 = bm + wm * 64 + mi * 16 + gid;
#pragma unroll
            for (int ni = 0; ni < 4; ni++) {
                const int n0 = bn + wn * 32 + ni * 8 + tig * 2;
                *(float2*)(Cout + (size_t)m0 * 1024 + n0) =
                    make_float2(acc[mi][ni][0], acc[mi][ni][1]);
                *(float2*)(Cout + (size_t)(m0 + 8) * 1024 + n0) =
                    make_float2(acc[mi][ni][2], acc[mi][ni][3]);
            }
        }
    } else {
#pragma unroll
        for (int mi = 0; mi < 4; mi++) {
            const int m0 = bm + wm * 64 + mi * 16 + gid;
#pragma unroll
            for (int ni = 0; ni < 4; ni++) {
                const int n0 = bn + wn * 32 + ni * 8 + tig * 2;
                const int which = n0 >> 10;
                const int rem = n0 & 1023;
                const int h = rem >> 6;
                const int d = rem & 63;
                float* basep = (which == 0) ? g_q : (which == 1) ? g_k : g_v;
#pragma unroll
                for (int half = 0; half < 2; half++) {
                    const int m = m0 + half * 8;
                    const int b = m >> 11;
                    const int t = m & 2047;
                    *(float2*)(basep + ((size_t)(b * HH + h) * TT + t) * DKK + d) =
                        make_float2(acc[mi][ni][2 * half], acc[mi][ni][2 * half + 1]);
                }
            }
        }
    }
}

// ---------------------------------------------------------------------------
// Flash attention fp32, causal (unchanged, known-good).
// ---------------------------------------------------------------------------
#define SROW 68
#define ATT_SMEM (4 * 64 * SROW * 4)

__global__ __launch_bounds__(128) void attn_kernel()
{
    extern __shared__ float sm[];
    float* Qs = sm;
    float* Ks = sm + 64 * SROW;
    float* Vs = sm + 2 * 64 * SROW;
    float* Ps = sm + 3 * 64 * SROW;

    const int tid = threadIdx.x;
    const int tx  = tid & 7;
    const int ty  = tid >> 3;
    const int qt  = gridDim.x - 1 - blockIdx.x;
    const int h   = blockIdx.y;
    const int b   = blockIdx.z;
    const int q0  = qt * 64;

    const float* Qg = g_q + (size_t)((b * HH + h) * TT) * DKK;
    const float* Kg = g_k + (size_t)((b * HH + h) * TT) * DKK;
    const float* Vg = g_v + (size_t)((b * HH + h) * TT) * DKK;

#pragma unroll
    for (int it = 0; it < 8; it++) {
        int lin = tid + it * 128;
        int row = lin >> 4;
        int c4  = (lin & 15) * 4;
        *(float4*)&Qs[row * SROW + c4] =
            *(const float4*)&Qg[(size_t)(q0 + row) * DKK + c4];
    }

    float o[4][8];
    float mrow[4], lrow[4];
#pragma unroll
    for (int i = 0; i < 4; i++) {
        mrow[i] = -1e30f; lrow[i] = 0.f;
#pragma unroll
        for (int j = 0; j < 8; j++) o[i][j] = 0.f;
    }

    for (int jt = 0; jt <= qt; jt++) {
        __syncthreads();
        int k0 = jt * 64;
#pragma unroll
        for (int it = 0; it < 8; it++) {
            int lin = tid + it * 128;
            int row = lin >> 4;
            int c4  = (lin & 15) * 4;
            *(float4*)&Ks[row * SROW + c4] =
                *(const float4*)&Kg[(size_t)(k0 + row) * DKK + c4];
            *(float4*)&Vs[row * SROW + c4] =
                *(const float4*)&Vg[(size_t)(k0 + row) * DKK + c4];
        }
        __syncthreads();

        float s[4][8];
#pragma unroll
        for (int i = 0; i < 4; i++)
#pragma unroll
            for (int j = 0; j < 8; j++) s[i][j] = 0.f;

#pragma unroll 8
        for (int d = 0; d < 64; d++) {
            float qv[4], kv[8];
#pragma unroll
            for (int i = 0; i < 4; i++) qv[i] = Qs[(4 * ty + i) * SROW + d];
#pragma unroll
            for (int j = 0; j < 8; j++) kv[j] = Ks[(8 * j + tx) * SROW + d];
#pragma unroll
            for (int i = 0; i < 4; i++)
#pragma unroll
                for (int j = 0; j < 8; j++)
                    s[i][j] = fmaf(qv[i], kv[j], s[i][j]);
        }

        const float sc = 0.125f;
        const bool diag = (jt == qt);
#pragma unroll
        for (int i = 0; i < 4; i++)
#pragma unroll
            for (int j = 0; j < 8; j++) {
                float v = s[i][j] * sc;
                if (diag && (k0 + 8 * j + tx) > (q0 + 4 * ty + i)) v = -1e30f;
                s[i][j] = v;
            }

        float alpha[4];
#pragma unroll
        for (int i = 0; i < 4; i++) {
            float mloc = s[i][0];
#pragma unroll
            for (int j = 1; j < 8; j++) mloc = fmaxf(mloc, s[i][j]);
            mloc = fmaxf(mloc, __shfl_xor_sync(0xffffffffu, mloc, 1));
            mloc = fmaxf(mloc, __shfl_xor_sync(0xffffffffu, mloc, 2));
            mloc = fmaxf(mloc, __shfl_xor_sync(0xffffffffu, mloc, 4));
            float mnew = fmaxf(mrow[i], mloc);
            alpha[i] = __expf(mrow[i] - mnew);
            float lsum = 0.f;
#pragma unroll
            for (int j = 0; j < 8; j++) {
                s[i][j] = __expf(s[i][j] - mnew);
                lsum += s[i][j];
            }
            lsum += __shfl_xor_sync(0xffffffffu, lsum, 1);
            lsum += __shfl_xor_sync(0xffffffffu, lsum, 2);
            lsum += __shfl_xor_sync(0xffffffffu, lsum, 4);
            lrow[i] = lrow[i] * alpha[i] + lsum;
            mrow[i] = mnew;
        }

#pragma unroll
        for (int i = 0; i < 4; i++)
#pragma unroll
            for (int j = 0; j < 8; j++) o[i][j] *= alpha[i];

#pragma unroll
        for (int i = 0; i < 4; i++)
#pragma unroll
            for (int j = 0; j < 8; j++)
                Ps[(4 * ty + i) * SROW + 8 * j + tx] = s[i][j];
        __syncthreads();

#pragma unroll 8
        for (int kk = 0; kk < 64; kk++) {
            float pv[4], vv[8];
#pragma unroll
            for (int i = 0; i < 4; i++) pv[i] = Ps[(4 * ty + i) * SROW + kk];
#pragma unroll
            for (int j = 0; j < 8; j++) vv[j] = Vs[kk * SROW + 8 * j + tx];
#pragma unroll
            for (int i = 0; i < 4; i++)
#pragma unroll
                for (int j = 0; j < 8; j++)
                    o[i][j] = fmaf(pv[i], vv[j], o[i][j]);
        }
    }

    __syncthreads();
#pragma unroll
    for (int i = 0; i < 4; i++) {
        float inv = 1.f / lrow[i];
#pragma unroll
        for (int j = 0; j < 8; j++)
            Ps[(4 * ty + i) * SROW + 8 * j + tx] = o[i][j] * inv;
    }
    __syncthreads();
#pragma unroll
    for (int it = 0; it < 8; it++) {
        int lin = tid + it * 128;
        int row = lin >> 4;
        int c4  = (lin & 15) * 4;
        float4 v = *(float4*)&Ps[row * SROW + c4];
        int t = q0 + row;
        *(float4*)&g_att[(size_t)(b * TT + t) * CC + h * DKK + c4] = v;
    }
}

// ---------------------------------------------------------------------------
extern "C" void kernel_launch(void* const* d_in, const int* in_sizes, int n_in,
                              void* d_out, int out_size)
{
    const float* x      = (const float*)d_in[0];   // [2, 2048, 1024]
    const float* w_attn = (const float*)d_in[1];   // [3072, 1024]
    const float* w_proj = (const float*)d_in[2];   // [1024, 1024]
    float* out = (float*)d_out;                    // [2, 2048, 1024]

    cudaFuncSetAttribute(attn_kernel,
                         cudaFuncAttributeMaxDynamicSharedMemorySize, ATT_SMEM);

    void *xs, *was, *wps, *atts, *attp;
    cudaGetSymbolAddress(&xs,   g_xs);
    cudaGetSymbolAddress(&was,  g_was);
    cudaGetSymbolAddress(&wps,  g_wps);
    cudaGetSymbolAddress(&atts, g_atts);
    cudaGetSymbolAddress(&attp, g_att);

    // 0) 3-block splits: A-side [hi|lo|hi], B-side [hi|hi|lo]
    split_kernel<<<(BB*TT*CC/4 + 255)/256, 256>>>(x,      (__nv_bfloat16*)xs,  BB*TT*CC, 0);
    split_kernel<<<(3*CC*CC/4  + 255)/256, 256>>>(w_attn, (__nv_bfloat16*)was, 3*CC*CC, 1);
    split_kernel<<<(CC*CC/4    + 255)/256, 256>>>(w_proj, (__nv_bfloat16*)wps, CC*CC, 1);

    // 1) QKV projection (bf16 mma.sync, K=3072), scatter to per-head fp32
    {
        dim3 grid(3 * CC / 128, (BB * TT) / 128);  // (24, 32)
        hgemm_nt<<<grid, 256>>>((const __nv_bfloat16*)xs, (const __nv_bfloat16*)was,
                                nullptr, 1);
    }

    // 2) causal flash attention (fp32)
    {
        dim3 grid(TT / 64, HH, BB);                // (32, 16, 2)
        attn_kernel<<<grid, 128, ATT_SMEM>>>();
    }

    // 3) split attention output (A-side), then output projection
    split_kernel<<<(BB*TT*CC/4 + 255)/256, 256>>>((const float*)attp,
                                                  (__nv_bfloat16*)atts, BB*TT*CC, 0);
    {
        dim3 grid(CC / 128, (BB * TT) / 128);      // (8, 32)
        hgemm_nt<<<grid, 256>>>((const __nv_bfloat16*)atts, (const __nv_bfloat16*)wps,
                                out, 0);
    }
}

// round 7
// speedup vs baseline: 2.3228x; 1.5142x over previous
#include <cuda_runtime.h>
#include <cuda_bf16.h>
#include <math.h>
#include <cstdint>

#define BB 2
#define TT 2048
#define CC 1024
#define HH 16
#define DKK 64
#define K3 3072   // tripled K: [hi|lo|hi] x [hi|hi|lo]

// bf16 scratch
__device__ __nv_bfloat16 g_qh[(size_t)BB*HH*TT*DKK];
__device__ __nv_bfloat16 g_ql[(size_t)BB*HH*TT*DKK];
__device__ __nv_bfloat16 g_kh[(size_t)BB*HH*TT*DKK];
__device__ __nv_bfloat16 g_kl[(size_t)BB*HH*TT*DKK];
__device__ __nv_bfloat16 g_vth[(size_t)BB*HH*DKK*TT];  // V^T [b,h,d,t]
__device__ __nv_bfloat16 g_vtl[(size_t)BB*HH*DKK*TT];
__device__ __nv_bfloat16 g_xs[(size_t)BB*TT*K3];       // x'      [4096, 3072]
__device__ __nv_bfloat16 g_was[(size_t)3*CC*K3];       // w_attn' [3072, 3072]
__device__ __nv_bfloat16 g_wps[(size_t)CC*K3];         // w_proj' [1024, 3072]
__device__ __nv_bfloat16 g_atts[(size_t)BB*TT*K3];     // att'    [4096, 3072]

__device__ __forceinline__ uint32_t smem_u32(const void* p) {
    uint32_t a;
    asm("{ .reg .u64 t; cvta.to.shared.u64 t, %1; cvt.u32.u64 %0, t; }" : "=r"(a) : "l"(p));
    return a;
}

// pack two floats -> bf16x2 register (a in low half, b in high half)
__device__ __forceinline__ uint32_t pack_bf16(float a, float b) {
    uint32_t r;
    asm("cvt.rn.bf16x2.f32 %0, %1, %2;" : "=r"(r) : "f"(b), "f"(a));
    return r;
}
__device__ __forceinline__ float bf16lo_f(uint32_t r) { return __uint_as_float(r << 16); }
__device__ __forceinline__ float bf16hi_f(uint32_t r) { return __uint_as_float(r & 0xFFFF0000u); }

#define MMA16816(d, a0,a1,a2,a3, b0,b1) \
    asm volatile("mma.sync.aligned.m16n8k16.row.col.f32.bf16.bf16.f32 " \
        "{%0,%1,%2,%3}, {%4,%5,%6,%7}, {%8,%9}, {%0,%1,%2,%3};" \
        : "+f"((d)[0]), "+f"((d)[1]), "+f"((d)[2]), "+f"((d)[3]) \
        : "r"(a0), "r"(a1), "r"(a2), "r"(a3), "r"(b0), "r"(b1))

#define LDSM4(r0,r1,r2,r3, addr) \
    asm volatile("ldmatrix.sync.aligned.m8n8.x4.shared.b16 {%0,%1,%2,%3}, [%4];" \
        : "=r"(r0), "=r"(r1), "=r"(r2), "=r"(r3) : "r"(addr))

#define CPA16(dst, src) \
    asm volatile("cp.async.cg.shared.global [%0], [%1], 16;" :: "r"(dst), "l"(src))

// ---------------------------------------------------------------------------
// split: fp32 [R,1024] -> bf16 [R,3072]. mode 0: [hi|lo|hi]  mode 1: [hi|hi|lo]
// ---------------------------------------------------------------------------
__global__ __launch_bounds__(256) void split_kernel(const float* __restrict__ in,
                                                    __nv_bfloat16* __restrict__ out,
                                                    int n, int mode)
{
    int i4 = (blockIdx.x * 256 + threadIdx.x) * 4;
    if (i4 >= n) return;
    float4 v = *(const float4*)(in + i4);
    int r = i4 >> 10;
    int c = i4 & 1023;
    __nv_bfloat16 h0 = __float2bfloat16(v.x);
    __nv_bfloat16 h1 = __float2bfloat16(v.y);
    __nv_bfloat16 h2 = __float2bfloat16(v.z);
    __nv_bfloat16 h3 = __float2bfloat16(v.w);
    __nv_bfloat16 l0 = __float2bfloat16(v.x - __bfloat162float(h0));
    __nv_bfloat16 l1 = __float2bfloat16(v.y - __bfloat162float(h1));
    __nv_bfloat16 l2 = __float2bfloat16(v.z - __bfloat162float(h2));
    __nv_bfloat16 l3 = __float2bfloat16(v.w - __bfloat162float(h3));
    __nv_bfloat162 hA = __nv_bfloat162(h0, h1), hB = __nv_bfloat162(h2, h3);
    __nv_bfloat162 lA = __nv_bfloat162(l0, l1), lB = __nv_bfloat162(l2, l3);
    __nv_bfloat162* p0 = (__nv_bfloat162*)(out + (size_t)r * K3 + c);
    __nv_bfloat162* p1 = (__nv_bfloat162*)(out + (size_t)r * K3 + 1024 + c);
    __nv_bfloat162* p2 = (__nv_bfloat162*)(out + (size_t)r * K3 + 2048 + c);
    p0[0] = hA; p0[1] = hB;
    if (mode == 0) { p1[0] = lA; p1[1] = lB; p2[0] = hA; p2[1] = hB; }
    else           { p1[0] = hA; p1[1] = hB; p2[0] = lA; p2[1] = lB; }
}

// ---------------------------------------------------------------------------
// bf16 GEMM NT (verified): C = A'B'^T, K=3072. CTA 128x128, BK=32, 8 warps.
// mode 0: fp32 C, ld=1024.  mode 1: QKV epilogue -> bf16 hi/lo (+ V transposed)
// ---------------------------------------------------------------------------
#define RS 40
#define NCH (K3 / 32)

__global__ __launch_bounds__(256) void hgemm_nt(const __nv_bfloat16* __restrict__ A,
                                                const __nv_bfloat16* __restrict__ Bw,
                                                float* __restrict__ Cout,
                                                int mode)
{
    __shared__ __align__(16) __nv_bfloat16 sA[2][128 * RS];
    __shared__ __align__(16) __nv_bfloat16 sB[2][128 * RS];

    const int tid  = threadIdx.x;
    const int lane = tid & 31;
    const int warp = tid >> 5;
    const int wm   = warp & 1;
    const int wn   = warp >> 1;
    const int bm   = blockIdx.y * 128;
    const int bn   = blockIdx.x * 128;

    const int r0 = tid >> 2, o0 = tid & 3;
    const int r1 = (tid + 256) >> 2, o1 = (tid + 256) & 3;

    const __nv_bfloat16* Ag = A  + (size_t)(bm) * K3;
    const __nv_bfloat16* Bg = Bw + (size_t)(bn) * K3;

    uint32_t sa0[2], sa1[2], sb0[2], sb1[2];
#pragma unroll
    for (int s = 0; s < 2; s++) {
        sa0[s] = smem_u32(&sA[s][r0 * RS + o0 * 8]);
        sa1[s] = smem_u32(&sA[s][r1 * RS + o1 * 8]);
        sb0[s] = smem_u32(&sB[s][r0 * RS + o0 * 8]);
        sb1[s] = smem_u32(&sB[s][r1 * RS + o1 * 8]);
    }

#define ISSUE_STAGE(buf, ch) do {                                              \
    const __nv_bfloat16* ap0 = Ag + (size_t)r0 * K3 + (ch) * 32 + o0 * 8;      \
    const __nv_bfloat16* ap1 = Ag + (size_t)r1 * K3 + (ch) * 32 + o1 * 8;      \
    const __nv_bfloat16* bp0 = Bg + (size_t)r0 * K3 + (ch) * 32 + o0 * 8;      \
    const __nv_bfloat16* bp1 = Bg + (size_t)r1 * K3 + (ch) * 32 + o1 * 8;      \
    CPA16(sa0[buf], ap0); CPA16(sa1[buf], ap1);                                \
    CPA16(sb0[buf], bp0); CPA16(sb1[buf], bp1);                                \
    asm volatile("cp.async.commit_group;");                                    \
} while (0)

    ISSUE_STAGE(0, 0);
    ISSUE_STAGE(1, 1);

    float acc[4][4][4];
#pragma unroll
    for (int mi = 0; mi < 4; mi++)
#pragma unroll
        for (int ni = 0; ni < 4; ni++)
#pragma unroll
            for (int r = 0; r < 4; r++) acc[mi][ni][r] = 0.f;

    const int l16 = lane & 15;

    for (int c = 0; c < NCH; c++) {
        const int buf = c & 1;
        asm volatile("cp.async.wait_group 1;");
        __syncthreads();

        const __nv_bfloat16* sAb = sA[buf];
        const __nv_bfloat16* sBb = sB[buf];

#pragma unroll
        for (int kk = 0; kk < 2; kk++) {
            uint32_t af[4][4];
            uint32_t bf[4][2];
#pragma unroll
            for (int mi = 0; mi < 4; mi++) {
                uint32_t addr = smem_u32(&sAb[(wm * 64 + mi * 16 + (lane & 15)) * RS
                                              + kk * 16 + (lane >> 4) * 8]);
                LDSM4(af[mi][0], af[mi][1], af[mi][2], af[mi][3], addr);
            }
#pragma unroll
            for (int ni = 0; ni < 4; ni++) {
                uint32_t addr = smem_u32(&sBb[(wn * 32 + ni * 8 + (l16 & 7)) * RS
                                              + kk * 16 + (l16 >> 3) * 8]);
                asm volatile("ldmatrix.sync.aligned.m8n8.x2.shared.b16 {%0,%1}, [%2];"
                             : "=r"(bf[ni][0]), "=r"(bf[ni][1]) : "r"(addr));
            }
#pragma unroll
            for (int mi = 0; mi < 4; mi++)
#pragma unroll
                for (int ni = 0; ni < 4; ni++)
                    MMA16816(acc[mi][ni], af[mi][0], af[mi][1], af[mi][2], af[mi][3],
                             bf[ni][0], bf[ni][1]);
        }

        __syncthreads();
        if (c + 2 < NCH) ISSUE_STAGE(buf, c + 2);
    }

    const int gid = lane >> 2;
    const int tig = lane & 3;
    if (mode == 0) {
#pragma unroll
        for (int mi = 0; mi < 4; mi++) {
            const int m0 = bm + wm * 64 + mi * 16 + gid;
#pragma unroll
            for (int ni = 0; ni < 4; ni++) {
                const int n0 = bn + wn * 32 + ni * 8 + tig * 2;
                *(float2*)(Cout + (size_t)m0 * 1024 + n0) =
                    make_float2(acc[mi][ni][0], acc[mi][ni][1]);
                *(float2*)(Cout + (size_t)(m0 + 8) * 1024 + n0) =
                    make_float2(acc[mi][ni][2], acc[mi][ni][3]);
            }
        }
    } else {
        // QKV epilogue: bf16 hi/lo split; q,k row-major per head; v transposed
#pragma unroll
        for (int mi = 0; mi < 4; mi++) {
            const int m0 = bm + wm * 64 + mi * 16 + gid;
#pragma unroll
            for (int ni = 0; ni < 4; ni++) {
                const int n0 = bn + wn * 32 + ni * 8 + tig * 2;
                const int which = n0 >> 10;
                const int rem = n0 & 1023;
                const int h = rem >> 6;
                const int d = rem & 63;
#pragma unroll
                for (int half = 0; half < 2; half++) {
                    const int m = m0 + half * 8;
                    const int b = m >> 11;
                    const int t = m & 2047;
                    const size_t bh = (size_t)(b * HH + h);
                    float v0 = acc[mi][ni][2 * half];
                    float v1 = acc[mi][ni][2 * half + 1];
                    uint32_t hi2 = pack_bf16(v0, v1);
                    float lo0 = v0 - bf16lo_f(hi2);
                    float lo1 = v1 - bf16hi_f(hi2);
                    uint32_t lo2 = pack_bf16(lo0, lo1);
                    if (which == 2) {
                        const size_t base = bh * DKK * TT + (size_t)t;
                        g_vth[base + (size_t)d * TT]       = __float2bfloat16(v0);
                        g_vth[base + (size_t)(d + 1) * TT] = __float2bfloat16(v1);
                        g_vtl[base + (size_t)d * TT]       = __float2bfloat16(lo0);
                        g_vtl[base + (size_t)(d + 1) * TT] = __float2bfloat16(lo1);
                    } else {
                        const size_t off = bh * TT * DKK + (size_t)t * DKK + d;
                        __nv_bfloat16* ph = (which == 0) ? g_qh : g_kh;
                        __nv_bfloat16* pl = (which == 0) ? g_ql : g_kl;
                        *(uint32_t*)(ph + off) = hi2;
                        *(uint32_t*)(pl + off) = lo2;
                    }
                }
            }
        }
    }
}

// ---------------------------------------------------------------------------
// Tensor-core flash attention, causal. q-tile 128, k-tile 64, 256 thr, 8 warps.
// S = Qh*Kh + Ql*Kh + Qh*Kl ; fp32 softmax ; O = Ph*Vh + Pl*Vh + Ph*Vl
// Output written directly to g_atts in [hi|lo|hi] layout.
// ---------------------------------------------------------------------------
#define QTILE 128
#define KTILE 64
#define ARS 72
#define QELEMS (QTILE * ARS)            // 9216
#define KTELEMS (KTILE * ARS)           // 4608
#define STG0 (2 * QELEMS)               // 18432
#define STG_STRIDE (4 * KTELEMS)        // 18432
#define ATT_SMEM_B ((STG0 + 2 * STG_STRIDE) * 2)   // 110592 bytes

__global__ __launch_bounds__(256) void attn_mma()
{
    extern __shared__ __align__(16) __nv_bfloat16 sm[];

    const int tid  = threadIdx.x;
    const int lane = tid & 31;
    const int w    = tid >> 5;
    const int qt   = gridDim.x - 1 - blockIdx.x;
    const int h    = blockIdx.y;
    const int b    = blockIdx.z;
    const int q0   = qt * QTILE;
    const size_t bh = (size_t)(b * HH + h);
    const int njt  = 2 * qt + 2;

    const __nv_bfloat16* Qh = g_qh + bh * TT * DKK;
    const __nv_bfloat16* Ql = g_ql + bh * TT * DKK;
    const __nv_bfloat16* Kh = g_kh + bh * TT * DKK;
    const __nv_bfloat16* Kl = g_kl + bh * TT * DKK;
    const __nv_bfloat16* Vh = g_vth + bh * DKK * TT;
    const __nv_bfloat16* Vl = g_vtl + bh * DKK * TT;

    // ---- Q tile cp.async (hi+lo): 128 rows x 8 chunks x 2 arrays ----
#pragma unroll
    for (int i = 0; i < 8; i++) {
        int lin = tid + i * 256;          // 0..2047
        int arr = lin >> 10;              // 0: hi, 1: lo
        int r   = (lin & 1023) >> 3;      // 0..127
        int ch  = lin & 7;                // 0..7
        const __nv_bfloat16* src = (arr ? Ql : Qh) + (size_t)(q0 + r) * DKK + ch * 8;
        uint32_t dst = smem_u32(&sm[arr * QELEMS + r * ARS + ch * 8]);
        CPA16(dst, src);
    }

    const int lr = tid >> 3, lch = tid & 7;   // lr 0..31, lch 0..7
#define ISSUE_KV(jt, s) do {                                                      \
    int k0_ = (jt) * KTILE;                                                       \
    __nv_bfloat16* base = sm + STG0 + (s) * STG_STRIDE;                           \
    CPA16(smem_u32(&base[lr * ARS + lch * 8]),                                    \
          Kh + (size_t)(k0_ + lr) * DKK + lch * 8);                               \
    CPA16(smem_u32(&base[(lr + 32) * ARS + lch * 8]),                             \
          Kh + (size_t)(k0_ + lr + 32) * DKK + lch * 8);                          \
    CPA16(smem_u32(&base[KTELEMS + lr * ARS + lch * 8]),                          \
          Kl + (size_t)(k0_ + lr) * DKK + lch * 8);                               \
    CPA16(smem_u32(&base[KTELEMS + (lr + 32) * ARS + lch * 8]),                   \
          Kl + (size_t)(k0_ + lr + 32) * DKK + lch * 8);                          \
    CPA16(smem_u32(&base[2 * KTELEMS + lr * ARS + lch * 8]),                      \
          Vh + (size_t)lr * TT + k0_ + lch * 8);                                  \
    CPA16(smem_u32(&base[2 * KTELEMS + (lr + 32) * ARS + lch * 8]),               \
          Vh + (size_t)(lr + 32) * TT + k0_ + lch * 8);                           \
    CPA16(smem_u32(&base[3 * KTELEMS + lr * ARS + lch * 8]),                      \
          Vl + (size_t)lr * TT + k0_ + lch * 8);                                  \
    CPA16(smem_u32(&base[3 * KTELEMS + (lr + 32) * ARS + lch * 8]),               \
          Vl + (size_t)(lr + 32) * TT + k0_ + lch * 8);                           \
    asm volatile("cp.async.commit_group;");                                       \
} while (0)

    ISSUE_KV(0, 0);        // group 0 (with Q)
    ISSUE_KV(1, 1);        // group 1

    float oacc[8][4];
#pragma unroll
    for (int ni = 0; ni < 8; ni++)
#pragma unroll
        for (int r = 0; r < 4; r++) oacc[ni][r] = 0.f;
    float mrow[2] = {-1e30f, -1e30f};
    float lrow[2] = {0.f, 0.f};

    uint32_t ah[4][4];     // persistent Qhi A-frags
    bool ah_loaded = false;

    const int arow = w * 16 + (lane & 15);
    const int acol8 = (lane >> 4) * 8;
    const int brow = (lane & 7) + ((lane & 16) ? 8 : 0);
    const int bcol8 = (lane & 8) ? 8 : 0;
    const int rr = lane >> 2;
    const int cc2 = (lane & 3) * 2;

    for (int jt = 0; jt < njt; jt++) {
        const int s = jt & 1;
        asm volatile("cp.async.wait_group 1;");
        __syncthreads();

        __nv_bfloat16* sKh = sm + STG0 + s * STG_STRIDE;
        __nv_bfloat16* sKl = sKh + KTELEMS;
        __nv_bfloat16* sVh = sKh + 2 * KTELEMS;
        __nv_bfloat16* sVl = sKh + 3 * KTELEMS;

        if (!ah_loaded) {
            ah_loaded = true;
#pragma unroll
            for (int kk = 0; kk < 4; kk++) {
                uint32_t addr = smem_u32(&sm[arow * ARS + kk * 16 + acol8]);
                LDSM4(ah[kk][0], ah[kk][1], ah[kk][2], ah[kk][3], addr);
            }
        }

        // ---- S = Q K^T (3-block) ----
        float sacc[8][4];
#pragma unroll
        for (int ni = 0; ni < 8; ni++)
#pragma unroll
            for (int r = 0; r < 4; r++) sacc[ni][r] = 0.f;

#pragma unroll
        for (int kk = 0; kk < 4; kk++) {
            uint32_t al[4];
            {
                uint32_t addr = smem_u32(&sm[QELEMS + arow * ARS + kk * 16 + acol8]);
                LDSM4(al[0], al[1], al[2], al[3], addr);
            }
#pragma unroll
            for (int np = 0; np < 4; np++) {
                uint32_t b4[4];
                uint32_t addr = smem_u32(&sKh[(np * 16 + brow) * ARS + kk * 16 + bcol8]);
                LDSM4(b4[0], b4[1], b4[2], b4[3], addr);
                MMA16816(sacc[2*np],   ah[kk][0], ah[kk][1], ah[kk][2], ah[kk][3], b4[0], b4[1]);
                MMA16816(sacc[2*np+1], ah[kk][0], ah[kk][1], ah[kk][2], ah[kk][3], b4[2], b4[3]);
                MMA16816(sacc[2*np],   al[0], al[1], al[2], al[3], b4[0], b4[1]);
                MMA16816(sacc[2*np+1], al[0], al[1], al[2], al[3], b4[2], b4[3]);
            }
#pragma unroll
            for (int np = 0; np < 4; np++) {
                uint32_t b4[4];
                uint32_t addr = smem_u32(&sKl[(np * 16 + brow) * ARS + kk * 16 + bcol8]);
                LDSM4(b4[0], b4[1], b4[2], b4[3], addr);
                MMA16816(sacc[2*np],   ah[kk][0], ah[kk][1], ah[kk][2], ah[kk][3], b4[0], b4[1]);
                MMA16816(sacc[2*np+1], ah[kk][0], ah[kk][1], ah[kk][2], ah[kk][3], b4[2], b4[3]);
            }
        }

        // ---- scale + causal mask ----
        const int k0 = jt * KTILE;
        const int r0 = q0 + w * 16 + rr;
        const int r1 = r0 + 8;
        const bool need_mask = (k0 + KTILE - 1 > r0);
#pragma unroll
        for (int ni = 0; ni < 8; ni++) {
            const int col = k0 + ni * 8 + cc2;
#pragma unroll
            for (int c = 0; c < 2; c++) {
                sacc[ni][c]     *= 0.125f;
                sacc[ni][2 + c] *= 0.125f;
                if (need_mask) {
                    if (col + c > r0) sacc[ni][c]     = -1e30f;
                    if (col + c > r1) sacc[ni][2 + c] = -1e30f;
                }
            }
        }

        // ---- online softmax (fp32) ----
        float mx0 = -1e30f, mx1 = -1e30f;
#pragma unroll
        for (int ni = 0; ni < 8; ni++) {
            mx0 = fmaxf(mx0, fmaxf(sacc[ni][0], sacc[ni][1]));
            mx1 = fmaxf(mx1, fmaxf(sacc[ni][2], sacc[ni][3]));
        }
        mx0 = fmaxf(mx0, __shfl_xor_sync(0xffffffffu, mx0, 1));
        mx0 = fmaxf(mx0, __shfl_xor_sync(0xffffffffu, mx0, 2));
        mx1 = fmaxf(mx1, __shfl_xor_sync(0xffffffffu, mx1, 1));
        mx1 = fmaxf(mx1, __shfl_xor_sync(0xffffffffu, mx1, 2));
        const float mn0 = fmaxf(mrow[0], mx0);
        const float mn1 = fmaxf(mrow[1], mx1);
        const float al0 = __expf(mrow[0] - mn0);
        const float al1 = __expf(mrow[1] - mn1);
        mrow[0] = mn0; mrow[1] = mn1;
        float sum0 = 0.f, sum1 = 0.f;
#pragma unroll
        for (int ni = 0; ni < 8; ni++) {
            sacc[ni][0] = __expf(sacc[ni][0] - mn0); sum0 += sacc[ni][0];
            sacc[ni][1] = __expf(sacc[ni][1] - mn0); sum0 += sacc[ni][1];
            sacc[ni][2] = __expf(sacc[ni][2] - mn1); sum1 += sacc[ni][2];
            sacc[ni][3] = __expf(sacc[ni][3] - mn1); sum1 += sacc[ni][3];
        }
        sum0 += __shfl_xor_sync(0xffffffffu, sum0, 1);
        sum0 += __shfl_xor_sync(0xffffffffu, sum0, 2);
        sum1 += __shfl_xor_sync(0xffffffffu, sum1, 1);
        sum1 += __shfl_xor_sync(0xffffffffu, sum1, 2);
        lrow[0] = lrow[0] * al0 + sum0;
        lrow[1] = lrow[1] * al1 + sum1;
#pragma unroll
        for (int ni = 0; ni < 8; ni++) {
            oacc[ni][0] *= al0; oacc[ni][1] *= al0;
            oacc[ni][2] *= al1; oacc[ni][3] *= al1;
        }

        // ---- O += P V  (Ph*Vh + Pl*Vh + Ph*Vl) ----
#pragma unroll
        for (int kk = 0; kk < 4; kk++) {
            const int b2 = 2 * kk, b3 = 2 * kk + 1;
            uint32_t pah[4], pal[4];
            pah[0] = pack_bf16(sacc[b2][0], sacc[b2][1]);
            pah[1] = pack_bf16(sacc[b2][2], sacc[b2][3]);
            pah[2] = pack_bf16(sacc[b3][0], sacc[b3][1]);
            pah[3] = pack_bf16(sacc[b3][2], sacc[b3][3]);
            pal[0] = pack_bf16(sacc[b2][0] - bf16lo_f(pah[0]), sacc[b2][1] - bf16hi_f(pah[0]));
            pal[1] = pack_bf16(sacc[b2][2] - bf16lo_f(pah[1]), sacc[b2][3] - bf16hi_f(pah[1]));
            pal[2] = pack_bf16(sacc[b3][0] - bf16lo_f(pah[2]), sacc[b3][1] - bf16hi_f(pah[2]));
            pal[3] = pack_bf16(sacc[b3][2] - bf16lo_f(pah[3]), sacc[b3][3] - bf16hi_f(pah[3]));
#pragma unroll
            for (int dp = 0; dp < 4; dp++) {
                uint32_t v4[4];
                uint32_t addr = smem_u32(&sVh[(dp * 16 + brow) * ARS + kk * 16 + bcol8]);
                LDSM4(v4[0], v4[1], v4[2], v4[3], addr);
                MMA16816(oacc[2*dp],   pah[0], pah[1], pah[2], pah[3], v4[0], v4[1]);
                MMA16816(oacc[2*dp+1], pah[0], pah[1], pah[2], pah[3], v4[2], v4[3]);
                MMA16816(oacc[2*dp],   pal[0], pal[1], pal[2], pal[3], v4[0], v4[1]);
                MMA16816(oacc[2*dp+1], pal[0], pal[1], pal[2], pal[3], v4[2], v4[3]);
            }
#pragma unroll
            for (int dp = 0; dp < 4; dp++) {
                uint32_t v4[4];
                uint32_t addr = smem_u32(&sVl[(dp * 16 + brow) * ARS + kk * 16 + bcol8]);
                LDSM4(v4[0], v4[1], v4[2], v4[3], addr);
                MMA16816(oacc[2*dp],   pah[0], pah[1], pah[2], pah[3], v4[0], v4[1]);
                MMA16816(oacc[2*dp+1], pah[0], pah[1], pah[2], pah[3], v4[2], v4[3]);
            }
        }

        __syncthreads();
        if (jt + 2 < njt) ISSUE_KV(jt + 2, s);
    }

    // ---- epilogue: normalize, split hi/lo, write g_atts [hi|lo|hi] ----
    const float inv0 = 1.f / lrow[0];
    const float inv1 = 1.f / lrow[1];
    const int row0 = q0 + w * 16 + rr;
    const size_t m0 = (size_t)b * TT + row0;
    __nv_bfloat16* dst0 = g_atts + m0 * K3 + h * 64;
    __nv_bfloat16* dst1 = g_atts + (m0 + 8) * K3 + h * 64;
#pragma unroll
    for (int ni = 0; ni < 8; ni++) {
        const int d = ni * 8 + cc2;
        float v0 = oacc[ni][0] * inv0, v1 = oacc[ni][1] * inv0;
        float v2 = oacc[ni][2] * inv1, v3 = oacc[ni][3] * inv1;
        uint32_t h0 = pack_bf16(v0, v1);
        uint32_t l0 = pack_bf16(v0 - bf16lo_f(h0), v1 - bf16hi_f(h0));
        uint32_t h1 = pack_bf16(v2, v3);
        uint32_t l1 = pack_bf16(v2 - bf16lo_f(h1), v3 - bf16hi_f(h1));
        *(uint32_t*)(dst0 + d)        = h0;
        *(uint32_t*)(dst0 + 1024 + d) = l0;
        *(uint32_t*)(dst0 + 2048 + d) = h0;
        *(uint32_t*)(dst1 + d)        = h1;
        *(uint32_t*)(dst1 + 1024 + d) = l1;
        *(uint32_t*)(dst1 + 2048 + d) = h1;
    }
}

// ---------------------------------------------------------------------------
extern "C" void kernel_launch(void* const* d_in, const int* in_sizes, int n_in,
                              void* d_out, int out_size)
{
    const float* x      = (const float*)d_in[0];   // [2, 2048, 1024]
    const float* w_attn = (const float*)d_in[1];   // [3072, 1024]
    const float* w_proj = (const float*)d_in[2];   // [1024, 1024]
    float* out = (float*)d_out;                    // [2, 2048, 1024]

    cudaFuncSetAttribute(attn_mma,
                         cudaFuncAttributeMaxDynamicSharedMemorySize, ATT_SMEM_B);

    void *xs, *was, *wps, *atts;
    cudaGetSymbolAddress(&xs,   g_xs);
    cudaGetSymbolAddress(&was,  g_was);
    cudaGetSymbolAddress(&wps,  g_wps);
    cudaGetSymbolAddress(&atts, g_atts);

    // 0) 3-block splits of the fp32 inputs
    split_kernel<<<(BB*TT*CC/4 + 255)/256, 256>>>(x,      (__nv_bfloat16*)xs,  BB*TT*CC, 0);
    split_kernel<<<(3*CC*CC/4  + 255)/256, 256>>>(w_attn, (__nv_bfloat16*)was, 3*CC*CC, 1);
    split_kernel<<<(CC*CC/4    + 255)/256, 256>>>(w_proj, (__nv_bfloat16*)wps, CC*CC, 1);

    // 1) QKV projection -> bf16 hi/lo per-head tensors (V transposed)
    {
        dim3 grid(3 * CC / 128, (BB * TT) / 128);  // (24, 32)
        hgemm_nt<<<grid, 256>>>((const __nv_bfloat16*)xs, (const __nv_bfloat16*)was,
                                nullptr, 1);
    }

    // 2) causal flash attention on tensor cores -> g_atts [hi|lo|hi]
    {
        dim3 grid(TT / QTILE, HH, BB);             // (16, 16, 2)
        attn_mma<<<grid, 256, ATT_SMEM_B>>>();
    }

    // 3) output projection
    {
        dim3 grid(CC / 128, (BB * TT) / 128);      // (8, 32)
        hgemm_nt<<<grid, 256>>>((const __nv_bfloat16*)atts, (const __nv_bfloat16*)wps,
                                out, 0);
    }
}

// round 8
// speedup vs baseline: 2.5327x; 1.0904x over previous
#include <cuda_runtime.h>
#include <cuda_bf16.h>
#include <math.h>
#include <cstdint>

#define BB 2
#define TT 2048
#define CC 1024
#define HH 16
#define DKK 64
#define K2 2048   // [hi | lo] compact layout

// bf16 scratch
__device__ __nv_bfloat16 g_qh[(size_t)BB*HH*TT*DKK];
__device__ __nv_bfloat16 g_ql[(size_t)BB*HH*TT*DKK];
__device__ __nv_bfloat16 g_kh[(size_t)BB*HH*TT*DKK];
__device__ __nv_bfloat16 g_kl[(size_t)BB*HH*TT*DKK];
__device__ __nv_bfloat16 g_vth[(size_t)BB*HH*DKK*TT];  // V^T [b,h,d,t]
__device__ __nv_bfloat16 g_vtl[(size_t)BB*HH*DKK*TT];
__device__ __nv_bfloat16 g_xs[(size_t)BB*TT*K2];       // x'      [4096, 2048]
__device__ __nv_bfloat16 g_was[(size_t)3*CC*K2];       // w_attn' [3072, 2048]
__device__ __nv_bfloat16 g_wps[(size_t)CC*K2];         // w_proj' [1024, 2048]
__device__ __nv_bfloat16 g_atts[(size_t)BB*TT*K2];     // att'    [4096, 2048]

__device__ __forceinline__ uint32_t smem_u32(const void* p) {
    uint32_t a;
    asm("{ .reg .u64 t; cvta.to.shared.u64 t, %1; cvt.u32.u64 %0, t; }" : "=r"(a) : "l"(p));
    return a;
}

__device__ __forceinline__ uint32_t pack_bf16(float a, float b) {
    uint32_t r;
    asm("cvt.rn.bf16x2.f32 %0, %1, %2;" : "=r"(r) : "f"(b), "f"(a));
    return r;
}
__device__ __forceinline__ float bf16lo_f(uint32_t r) { return __uint_as_float(r << 16); }
__device__ __forceinline__ float bf16hi_f(uint32_t r) { return __uint_as_float(r & 0xFFFF0000u); }

#define MMA16816(d, a0,a1,a2,a3, b0,b1) \
    asm volatile("mma.sync.aligned.m16n8k16.row.col.f32.bf16.bf16.f32 " \
        "{%0,%1,%2,%3}, {%4,%5,%6,%7}, {%8,%9}, {%0,%1,%2,%3};" \
        : "+f"((d)[0]), "+f"((d)[1]), "+f"((d)[2]), "+f"((d)[3]) \
        : "r"(a0), "r"(a1), "r"(a2), "r"(a3), "r"(b0), "r"(b1))

#define LDSM4(r0,r1,r2,r3, addr) \
    asm volatile("ldmatrix.sync.aligned.m8n8.x4.shared.b16 {%0,%1,%2,%3}, [%4];" \
        : "=r"(r0), "=r"(r1), "=r"(r2), "=r"(r3) : "r"(addr))

#define CPA16(dst, src) \
    asm volatile("cp.async.cg.shared.global [%0], [%1], 16;" :: "r"(dst), "l"(src))

// ---------------------------------------------------------------------------
// split: fp32 [R,1024] -> bf16 [R,2048] = [hi | lo]
// ---------------------------------------------------------------------------
__global__ __launch_bounds__(256) void split_kernel(const float* __restrict__ in,
                                                    __nv_bfloat16* __restrict__ out,
                                                    int n)
{
    int i4 = (blockIdx.x * 256 + threadIdx.x) * 4;
    if (i4 >= n) return;
    float4 v = *(const float4*)(in + i4);
    int r = i4 >> 10;
    int c = i4 & 1023;
    __nv_bfloat16 h0 = __float2bfloat16(v.x);
    __nv_bfloat16 h1 = __float2bfloat16(v.y);
    __nv_bfloat16 h2 = __float2bfloat16(v.z);
    __nv_bfloat16 h3 = __float2bfloat16(v.w);
    __nv_bfloat16 l0 = __float2bfloat16(v.x - __bfloat162float(h0));
    __nv_bfloat16 l1 = __float2bfloat16(v.y - __bfloat162float(h1));
    __nv_bfloat16 l2 = __float2bfloat16(v.z - __bfloat162float(h2));
    __nv_bfloat16 l3 = __float2bfloat16(v.w - __bfloat162float(h3));
    __nv_bfloat162* ph = (__nv_bfloat162*)(out + (size_t)r * K2 + c);
    __nv_bfloat162* pl = (__nv_bfloat162*)(out + (size_t)r * K2 + 1024 + c);
    ph[0] = __nv_bfloat162(h0, h1); ph[1] = __nv_bfloat162(h2, h3);
    pl[0] = __nv_bfloat162(l0, l1); pl[1] = __nv_bfloat162(l2, l3);
}

// ---------------------------------------------------------------------------
// 3-term bf16 GEMM NT: C = Ah*Bh^T + Al*Bh^T + Ah*Bl^T over base K=1024.
// A,B stored [., 2048] = [hi|lo]. CTA 128x128, base-K chunk 32, 8 warps.
// Per stage: 4 tiles (Ah, Al, Bh, Bl) of 128x32 (padded RS=40).
// mode 0: fp32 C ld=1024.  mode 1: QKV epilogue -> bf16 hi/lo (+V transposed)
// ---------------------------------------------------------------------------
#define RS 40
#define NCHUNK 32
#define TILE_E (128 * RS)               // 5120 elements
#define TILE_B (TILE_E * 2)             // 10240 bytes
#define STAGE_E (4 * TILE_E)            // 20480 elements
#define STAGE_B (4 * TILE_B)            // 40960 bytes
#define GSMEM_B (2 * STAGE_B)           // 81920 bytes

__global__ __launch_bounds__(256, 2) void hgemm3_nt(const __nv_bfloat16* __restrict__ A,
                                                    const __nv_bfloat16* __restrict__ Bw,
                                                    float* __restrict__ Cout,
                                                    int mode)
{
    extern __shared__ __align__(16) __nv_bfloat16 sm3[];
    const uint32_t sbase = smem_u32(sm3);

    const int tid  = threadIdx.x;
    const int lane = tid & 31;
    const int warp = tid >> 5;
    const int wm   = warp & 1;
    const int wn   = warp >> 1;
    const int bm   = blockIdx.y * 128;
    const int bn   = blockIdx.x * 128;

    // loader: r0 = tid>>2 (0..63) and r0+64; o = tid&3 (16B chunk of 64B row)
    const int r0 = tid >> 2, o = tid & 3;
    const uint32_t e0b = (uint32_t)(r0 * RS + o * 8) * 2;
    const uint32_t e1b = (uint32_t)((r0 + 64) * RS + o * 8) * 2;

    const __nv_bfloat16* Ag = A  + (size_t)bm * K2;
    const __nv_bfloat16* Bg = Bw + (size_t)bn * K2;
    const __nv_bfloat16* a0p = Ag + (size_t)r0 * K2 + o * 8;
    const __nv_bfloat16* a1p = Ag + (size_t)(r0 + 64) * K2 + o * 8;
    const __nv_bfloat16* b0p = Bg + (size_t)r0 * K2 + o * 8;
    const __nv_bfloat16* b1p = Bg + (size_t)(r0 + 64) * K2 + o * 8;

#define ISSUE3(buf, ch) do {                                                   \
    const int ko = (ch) * 32;                                                  \
    const uint32_t base = sbase + (buf) * STAGE_B;                             \
    CPA16(base + e0b,              a0p + ko);                                  \
    CPA16(base + e1b,              a1p + ko);                                  \
    CPA16(base + TILE_B + e0b,     a0p + ko + 1024);                           \
    CPA16(base + TILE_B + e1b,     a1p + ko + 1024);                           \
    CPA16(base + 2*TILE_B + e0b,   b0p + ko);                                  \
    CPA16(base + 2*TILE_B + e1b,   b1p + ko);                                  \
    CPA16(base + 3*TILE_B + e0b,   b0p + ko + 1024);                           \
    CPA16(base + 3*TILE_B + e1b,   b1p + ko + 1024);                           \
    asm volatile("cp.async.commit_group;");                                    \
} while (0)

    ISSUE3(0, 0);
    ISSUE3(1, 1);

    float acc[4][4][4];
#pragma unroll
    for (int mi = 0; mi < 4; mi++)
#pragma unroll
        for (int ni = 0; ni < 4; ni++)
#pragma unroll
            for (int r = 0; r < 4; r++) acc[mi][ni][r] = 0.f;

    const int arow  = wm * 64 + (lane & 15);
    const int acol8 = (lane >> 4) * 8;
    const int brow  = (lane & 7) + ((lane & 16) ? 8 : 0);
    const int bcol8 = (lane & 8) ? 8 : 0;

    for (int c = 0; c < NCHUNK; c++) {
        const int buf = c & 1;
        if (c + 1 < NCHUNK) asm volatile("cp.async.wait_group 1;");
        else                asm volatile("cp.async.wait_group 0;");
        __syncthreads();

        const __nv_bfloat16* sAh = sm3 + buf * STAGE_E;
        const __nv_bfloat16* sAl = sAh + TILE_E;
        const __nv_bfloat16* sBh = sAh + 2 * TILE_E;
        const __nv_bfloat16* sBl = sAh + 3 * TILE_E;

#pragma unroll
        for (int kk = 0; kk < 2; kk++) {
            uint32_t ah[4][4], al[4][4];
#pragma unroll
            for (int mi = 0; mi < 4; mi++) {
                uint32_t addr = smem_u32(&sAh[(arow + mi * 16) * RS + kk * 16 + acol8]);
                LDSM4(ah[mi][0], ah[mi][1], ah[mi][2], ah[mi][3], addr);
            }
#pragma unroll
            for (int mi = 0; mi < 4; mi++) {
                uint32_t addr = smem_u32(&sAl[(arow + mi * 16) * RS + kk * 16 + acol8]);
                LDSM4(al[mi][0], al[mi][1], al[mi][2], al[mi][3], addr);
            }
            {
                uint32_t bh[2][4];
#pragma unroll
                for (int np = 0; np < 2; np++) {
                    uint32_t addr = smem_u32(&sBh[(wn * 32 + np * 16 + brow) * RS
                                                  + kk * 16 + bcol8]);
                    LDSM4(bh[np][0], bh[np][1], bh[np][2], bh[np][3], addr);
                }
#pragma unroll
                for (int mi = 0; mi < 4; mi++)
#pragma unroll
                    for (int np = 0; np < 2; np++) {
                        MMA16816(acc[mi][2*np],   ah[mi][0], ah[mi][1], ah[mi][2], ah[mi][3],
                                 bh[np][0], bh[np][1]);
                        MMA16816(acc[mi][2*np+1], ah[mi][0], ah[mi][1], ah[mi][2], ah[mi][3],
                                 bh[np][2], bh[np][3]);
                        MMA16816(acc[mi][2*np],   al[mi][0], al[mi][1], al[mi][2], al[mi][3],
                                 bh[np][0], bh[np][1]);
                        MMA16816(acc[mi][2*np+1], al[mi][0], al[mi][1], al[mi][2], al[mi][3],
                                 bh[np][2], bh[np][3]);
                    }
            }
            {
                uint32_t bl[2][4];
#pragma unroll
                for (int np = 0; np < 2; np++) {
                    uint32_t addr = smem_u32(&sBl[(wn * 32 + np * 16 + brow) * RS
                                                  + kk * 16 + bcol8]);
                    LDSM4(bl[np][0], bl[np][1], bl[np][2], bl[np][3], addr);
                }
#pragma unroll
                for (int mi = 0; mi < 4; mi++)
#pragma unroll
                    for (int np = 0; np < 2; np++) {
                        MMA16816(acc[mi][2*np],   ah[mi][0], ah[mi][1], ah[mi][2], ah[mi][3],
                                 bl[np][0], bl[np][1]);
                        MMA16816(acc[mi][2*np+1], ah[mi][0], ah[mi][1], ah[mi][2], ah[mi][3],
                                 bl[np][2], bl[np][3]);
                    }
            }
        }

        __syncthreads();
        if (c + 2 < NCHUNK) ISSUE3(buf, c + 2);
    }

    // epilogue (acc[mi][ni] covers n = bn + wn*32 + ni*8, same as before)
    const int gid = lane >> 2;
    const int tig = lane & 3;
    if (mode == 0) {
#pragma unroll
        for (int mi = 0; mi < 4; mi++) {
            const int m0 = bm + wm * 64 + mi * 16 + gid;
#pragma unroll
            for (int ni = 0; ni < 4; ni++) {
                const int n0 = bn + wn * 32 + ni * 8 + tig * 2;
                *(float2*)(Cout + (size_t)m0 * 1024 + n0) =
                    make_float2(acc[mi][ni][0], acc[mi][ni][1]);
                *(float2*)(Cout + (size_t)(m0 + 8) * 1024 + n0) =
                    make_float2(acc[mi][ni][2], acc[mi][ni][3]);
            }
        }
    } else {
#pragma unroll
        for (int mi = 0; mi < 4; mi++) {
            const int m0 = bm + wm * 64 + mi * 16 + gid;
#pragma unroll
            for (int ni = 0; ni < 4; ni++) {
                const int n0 = bn + wn * 32 + ni * 8 + tig * 2;
                const int which = n0 >> 10;
                const int rem = n0 & 1023;
                const int h = rem >> 6;
                const int d = rem & 63;
#pragma unroll
                for (int half = 0; half < 2; half++) {
                    const int m = m0 + half * 8;
                    const int b = m >> 11;
                    const int t = m & 2047;
                    const size_t bh = (size_t)(b * HH + h);
                    float v0 = acc[mi][ni][2 * half];
                    float v1 = acc[mi][ni][2 * half + 1];
                    uint32_t hi2 = pack_bf16(v0, v1);
                    float lo0 = v0 - bf16lo_f(hi2);
                    float lo1 = v1 - bf16hi_f(hi2);
                    uint32_t lo2 = pack_bf16(lo0, lo1);
                    if (which == 2) {
                        const size_t base = bh * DKK * TT + (size_t)t;
                        g_vth[base + (size_t)d * TT]       = __float2bfloat16(v0);
                        g_vth[base + (size_t)(d + 1) * TT] = __float2bfloat16(v1);
                        g_vtl[base + (size_t)d * TT]       = __float2bfloat16(lo0);
                        g_vtl[base + (size_t)(d + 1) * TT] = __float2bfloat16(lo1);
                    } else {
                        const size_t off = bh * TT * DKK + (size_t)t * DKK + d;
                        __nv_bfloat16* ph = (which == 0) ? g_qh : g_kh;
                        __nv_bfloat16* pl = (which == 0) ? g_ql : g_kl;
                        *(uint32_t*)(ph + off) = hi2;
                        *(uint32_t*)(pl + off) = lo2;
                    }
                }
            }
        }
    }
}

// ---------------------------------------------------------------------------
// Tensor-core flash attention, causal (verified R7). Output -> g_atts [hi|lo].
// ---------------------------------------------------------------------------
#define QTILE 128
#define KTILE 64
#define ARS 72
#define QELEMS (QTILE * ARS)
#define KTELEMS (KTILE * ARS)
#define STG0 (2 * QELEMS)
#define STG_STRIDE (4 * KTELEMS)
#define ATT_SMEM_B ((STG0 + 2 * STG_STRIDE) * 2)

__global__ __launch_bounds__(256) void attn_mma()
{
    extern __shared__ __align__(16) __nv_bfloat16 sm[];

    const int tid  = threadIdx.x;
    const int lane = tid & 31;
    const int w    = tid >> 5;
    const int qt   = gridDim.x - 1 - blockIdx.x;
    const int h    = blockIdx.y;
    const int b    = blockIdx.z;
    const int q0   = qt * QTILE;
    const size_t bh = (size_t)(b * HH + h);
    const int njt  = 2 * qt + 2;

    const __nv_bfloat16* Qh = g_qh + bh * TT * DKK;
    const __nv_bfloat16* Ql = g_ql + bh * TT * DKK;
    const __nv_bfloat16* Kh = g_kh + bh * TT * DKK;
    const __nv_bfloat16* Kl = g_kl + bh * TT * DKK;
    const __nv_bfloat16* Vh = g_vth + bh * DKK * TT;
    const __nv_bfloat16* Vl = g_vtl + bh * DKK * TT;

#pragma unroll
    for (int i = 0; i < 8; i++) {
        int lin = tid + i * 256;
        int arr = lin >> 10;
        int r   = (lin & 1023) >> 3;
        int ch  = lin & 7;
        const __nv_bfloat16* src = (arr ? Ql : Qh) + (size_t)(q0 + r) * DKK + ch * 8;
        uint32_t dst = smem_u32(&sm[arr * QELEMS + r * ARS + ch * 8]);
        CPA16(dst, src);
    }

    const int lr = tid >> 3, lch = tid & 7;
#define ISSUE_KV(jt, s) do {                                                      \
    int k0_ = (jt) * KTILE;                                                       \
    __nv_bfloat16* base = sm + STG0 + (s) * STG_STRIDE;                           \
    CPA16(smem_u32(&base[lr * ARS + lch * 8]),                                    \
          Kh + (size_t)(k0_ + lr) * DKK + lch * 8);                               \
    CPA16(smem_u32(&base[(lr + 32) * ARS + lch * 8]),                             \
          Kh + (size_t)(k0_ + lr + 32) * DKK + lch * 8);                          \
    CPA16(smem_u32(&base[KTELEMS + lr * ARS + lch * 8]),                          \
          Kl + (size_t)(k0_ + lr) * DKK + lch * 8);                               \
    CPA16(smem_u32(&base[KTELEMS + (lr + 32) * ARS + lch * 8]),                   \
          Kl + (size_t)(k0_ + lr + 32) * DKK + lch * 8);                          \
    CPA16(smem_u32(&base[2 * KTELEMS + lr * ARS + lch * 8]),                      \
          Vh + (size_t)lr * TT + k0_ + lch * 8);                                  \
    CPA16(smem_u32(&base[2 * KTELEMS + (lr + 32) * ARS + lch * 8]),               \
          Vh + (size_t)(lr + 32) * TT + k0_ + lch * 8);                           \
    CPA16(smem_u32(&base[3 * KTELEMS + lr * ARS + lch * 8]),                      \
          Vl + (size_t)lr * TT + k0_ + lch * 8);                                  \
    CPA16(smem_u32(&base[3 * KTELEMS + (lr + 32) * ARS + lch * 8]),               \
          Vl + (size_t)(lr + 32) * TT + k0_ + lch * 8);                           \
    asm volatile("cp.async.commit_group;");                                       \
} while (0)

    ISSUE_KV(0, 0);
    ISSUE_KV(1, 1);

    float oacc[8][4];
#pragma unroll
    for (int ni = 0; ni < 8; ni++)
#pragma unroll
        for (int r = 0; r < 4; r++) oacc[ni][r] = 0.f;
    float mrow[2] = {-1e30f, -1e30f};
    float lrow[2] = {0.f, 0.f};

    uint32_t ah[4][4];
    bool ah_loaded = false;

    const int arow = w * 16 + (lane & 15);
    const int acol8 = (lane >> 4) * 8;
    const int brow = (lane & 7) + ((lane & 16) ? 8 : 0);
    const int bcol8 = (lane & 8) ? 8 : 0;
    const int rr = lane >> 2;
    const int cc2 = (lane & 3) * 2;

    for (int jt = 0; jt < njt; jt++) {
        const int s = jt & 1;
        if (jt + 1 < njt) asm volatile("cp.async.wait_group 1;");
        else              asm volatile("cp.async.wait_group 0;");
        __syncthreads();

        __nv_bfloat16* sKh = sm + STG0 + s * STG_STRIDE;
        __nv_bfloat16* sKl = sKh + KTELEMS;
        __nv_bfloat16* sVh = sKh + 2 * KTELEMS;
        __nv_bfloat16* sVl = sKh + 3 * KTELEMS;

        if (!ah_loaded) {
            ah_loaded = true;
#pragma unroll
            for (int kk = 0; kk < 4; kk++) {
                uint32_t addr = smem_u32(&sm[arow * ARS + kk * 16 + acol8]);
                LDSM4(ah[kk][0], ah[kk][1], ah[kk][2], ah[kk][3], addr);
            }
        }

        float sacc[8][4];
#pragma unroll
        for (int ni = 0; ni < 8; ni++)
#pragma unroll
            for (int r = 0; r < 4; r++) sacc[ni][r] = 0.f;

#pragma unroll
        for (int kk = 0; kk < 4; kk++) {
            uint32_t al[4];
            {
                uint32_t addr = smem_u32(&sm[QELEMS + arow * ARS + kk * 16 + acol8]);
                LDSM4(al[0], al[1], al[2], al[3], addr);
            }
#pragma unroll
            for (int np = 0; np < 4; np++) {
                uint32_t b4[4];
                uint32_t addr = smem_u32(&sKh[(np * 16 + brow) * ARS + kk * 16 + bcol8]);
                LDSM4(b4[0], b4[1], b4[2], b4[3], addr);
                MMA16816(sacc[2*np],   ah[kk][0], ah[kk][1], ah[kk][2], ah[kk][3], b4[0], b4[1]);
                MMA16816(sacc[2*np+1], ah[kk][0], ah[kk][1], ah[kk][2], ah[kk][3], b4[2], b4[3]);
                MMA16816(sacc[2*np],   al[0], al[1], al[2], al[3], b4[0], b4[1]);
                MMA16816(sacc[2*np+1], al[0], al[1], al[2], al[3], b4[2], b4[3]);
            }
#pragma unroll
            for (int np = 0; np < 4; np++) {
                uint32_t b4[4];
                uint32_t addr = smem_u32(&sKl[(np * 16 + brow) * ARS + kk * 16 + bcol8]);
                LDSM4(b4[0], b4[1], b4[2], b4[3], addr);
                MMA16816(sacc[2*np],   ah[kk][0], ah[kk][1], ah[kk][2], ah[kk][3], b4[0], b4[1]);
                MMA16816(sacc[2*np+1], ah[kk][0], ah[kk][1], ah[kk][2], ah[kk][3], b4[2], b4[3]);
            }
        }

        const int k0 = jt * KTILE;
        const int r0 = q0 + w * 16 + rr;
        const int r1 = r0 + 8;
        const bool need_mask = (k0 + KTILE - 1 > r0);
#pragma unroll
        for (int ni = 0; ni < 8; ni++) {
            const int col = k0 + ni * 8 + cc2;
#pragma unroll
            for (int c = 0; c < 2; c++) {
                sacc[ni][c]     *= 0.125f;
                sacc[ni][2 + c] *= 0.125f;
                if (need_mask) {
                    if (col + c > r0) sacc[ni][c]     = -1e30f;
                    if (col + c > r1) sacc[ni][2 + c] = -1e30f;
                }
            }
        }

        float mx0 = -1e30f, mx1 = -1e30f;
#pragma unroll
        for (int ni = 0; ni < 8; ni++) {
            mx0 = fmaxf(mx0, fmaxf(sacc[ni][0], sacc[ni][1]));
            mx1 = fmaxf(mx1, fmaxf(sacc[ni][2], sacc[ni][3]));
        }
        mx0 = fmaxf(mx0, __shfl_xor_sync(0xffffffffu, mx0, 1));
        mx0 = fmaxf(mx0, __shfl_xor_sync(0xffffffffu, mx0, 2));
        mx1 = fmaxf(mx1, __shfl_xor_sync(0xffffffffu, mx1, 1));
        mx1 = fmaxf(mx1, __shfl_xor_sync(0xffffffffu, mx1, 2));
        const float mn0 = fmaxf(mrow[0], mx0);
        const float mn1 = fmaxf(mrow[1], mx1);
        const float al0 = __expf(mrow[0] - mn0);
        const float al1 = __expf(mrow[1] - mn1);
        mrow[0] = mn0; mrow[1] = mn1;
        float sum0 = 0.f, sum1 = 0.f;
#pragma unroll
        for (int ni = 0; ni < 8; ni++) {
            sacc[ni][0] = __expf(sacc[ni][0] - mn0); sum0 += sacc[ni][0];
            sacc[ni][1] = __expf(sacc[ni][1] - mn0); sum0 += sacc[ni][1];
            sacc[ni][2] = __expf(sacc[ni][2] - mn1); sum1 += sacc[ni][2];
            sacc[ni][3] = __expf(sacc[ni][3] - mn1); sum1 += sacc[ni][3];
        }
        sum0 += __shfl_xor_sync(0xffffffffu, sum0, 1);
        sum0 += __shfl_xor_sync(0xffffffffu, sum0, 2);
        sum1 += __shfl_xor_sync(0xffffffffu, sum1, 1);
        sum1 += __shfl_xor_sync(0xffffffffu, sum1, 2);
        lrow[0] = lrow[0] * al0 + sum0;
        lrow[1] = lrow[1] * al1 + sum1;
#pragma unroll
        for (int ni = 0; ni < 8; ni++) {
            oacc[ni][0] *= al0; oacc[ni][1] *= al0;
            oacc[ni][2] *= al1; oacc[ni][3] *= al1;
        }

#pragma unroll
        for (int kk = 0; kk < 4; kk++) {
            const int b2 = 2 * kk, b3 = 2 * kk + 1;
            uint32_t pah[4], pal[4];
            pah[0] = pack_bf16(sacc[b2][0], sacc[b2][1]);
            pah[1] = pack_bf16(sacc[b2][2], sacc[b2][3]);
            pah[2] = pack_bf16(sacc[b3][0], sacc[b3][1]);
            pah[3] = pack_bf16(sacc[b3][2], sacc[b3][3]);
            pal[0] = pack_bf16(sacc[b2][0] - bf16lo_f(pah[0]), sacc[b2][1] - bf16hi_f(pah[0]));
            pal[1] = pack_bf16(sacc[b2][2] - bf16lo_f(pah[1]), sacc[b2][3] - bf16hi_f(pah[1]));
            pal[2] = pack_bf16(sacc[b3][0] - bf16lo_f(pah[2]), sacc[b3][1] - bf16hi_f(pah[2]));
            pal[3] = pack_bf16(sacc[b3][2] - bf16lo_f(pah[3]), sacc[b3][3] - bf16hi_f(pah[3]));
#pragma unroll
            for (int dp = 0; dp < 4; dp++) {
                uint32_t v4[4];
                uint32_t addr = smem_u32(&sVh[(dp * 16 + brow) * ARS + kk * 16 + bcol8]);
                LDSM4(v4[0], v4[1], v4[2], v4[3], addr);
                MMA16816(oacc[2*dp],   pah[0], pah[1], pah[2], pah[3], v4[0], v4[1]);
                MMA16816(oacc[2*dp+1], pah[0], pah[1], pah[2], pah[3], v4[2], v4[3]);
                MMA16816(oacc[2*dp],   pal[0], pal[1], pal[2], pal[3], v4[0], v4[1]);
                MMA16816(oacc[2*dp+1], pal[0], pal[1], pal[2], pal[3], v4[2], v4[3]);
            }
#pragma unroll
            for (int dp = 0; dp < 4; dp++) {
                uint32_t v4[4];
                uint32_t addr = smem_u32(&sVl[(dp * 16 + brow) * ARS + kk * 16 + bcol8]);
                LDSM4(v4[0], v4[1], v4[2], v4[3], addr);
                MMA16816(oacc[2*dp],   pah[0], pah[1], pah[2], pah[3], v4[0], v4[1]);
                MMA16816(oacc[2*dp+1], pah[0], pah[1], pah[2], pah[3], v4[2], v4[3]);
            }
        }

        __syncthreads();
        if (jt + 2 < njt) ISSUE_KV(jt + 2, s);
    }

    // epilogue: normalize, hi/lo split, write g_atts [hi | lo]
    const float inv0 = 1.f / lrow[0];
    const float inv1 = 1.f / lrow[1];
    const int row0 = q0 + w * 16 + rr;
    const size_t m0 = (size_t)b * TT + row0;
    __nv_bfloat16* dst0 = g_atts + m0 * K2 + h * 64;
    __nv_bfloat16* dst1 = g_atts + (m0 + 8) * K2 + h * 64;
#pragma unroll
    for (int ni = 0; ni < 8; ni++) {
        const int d = ni * 8 + cc2;
        float v0 = oacc[ni][0] * inv0, v1 = oacc[ni][1] * inv0;
        float v2 = oacc[ni][2] * inv1, v3 = oacc[ni][3] * inv1;
        uint32_t h0 = pack_bf16(v0, v1);
        uint32_t l0 = pack_bf16(v0 - bf16lo_f(h0), v1 - bf16hi_f(h0));
        uint32_t h1 = pack_bf16(v2, v3);
        uint32_t l1 = pack_bf16(v2 - bf16lo_f(h1), v3 - bf16hi_f(h1));
        *(uint32_t*)(dst0 + d)        = h0;
        *(uint32_t*)(dst0 + 1024 + d) = l0;
        *(uint32_t*)(dst1 + d)        = h1;
        *(uint32_t*)(dst1 + 1024 + d) = l1;
    }
}

// ---------------------------------------------------------------------------
extern "C" void kernel_launch(void* const* d_in, const int* in_sizes, int n_in,
                              void* d_out, int out_size)
{
    const float* x      = (const float*)d_in[0];   // [2, 2048, 1024]
    const float* w_attn = (const float*)d_in[1];   // [3072, 1024]
    const float* w_proj = (const float*)d_in[2];   // [1024, 1024]
    float* out = (float*)d_out;                    // [2, 2048, 1024]

    cudaFuncSetAttribute(hgemm3_nt,
                         cudaFuncAttributeMaxDynamicSharedMemorySize, GSMEM_B);
    cudaFuncSetAttribute(attn_mma,
                         cudaFuncAttributeMaxDynamicSharedMemorySize, ATT_SMEM_B);

    void *xs, *was, *wps, *atts;
    cudaGetSymbolAddress(&xs,   g_xs);
    cudaGetSymbolAddress(&was,  g_was);
    cudaGetSymbolAddress(&wps,  g_wps);
    cudaGetSymbolAddress(&atts, g_atts);

    // 0) [hi|lo] splits of the fp32 inputs
    split_kernel<<<(BB*TT*CC/4 + 255)/256, 256>>>(x,      (__nv_bfloat16*)xs,  BB*TT*CC);
    split_kernel<<<(3*CC*CC/4  + 255)/256, 256>>>(w_attn, (__nv_bfloat16*)was, 3*CC*CC);
    split_kernel<<<(CC*CC/4    + 255)/256, 256>>>(w_proj, (__nv_bfloat16*)wps, CC*CC);

    // 1) QKV projection (3-term bf16 GEMM) -> bf16 hi/lo per-head (V transposed)
    {
        dim3 grid(3 * CC / 128, (BB * TT) / 128);  // (24, 32)
        hgemm3_nt<<<grid, 256, GSMEM_B>>>((const __nv_bfloat16*)xs,
                                          (const __nv_bfloat16*)was, nullptr, 1);
    }

    // 2) causal flash attention on tensor cores -> g_atts [hi|lo]
    {
        dim3 grid(TT / QTILE, HH, BB);             // (16, 16, 2)
        attn_mma<<<grid, 256, ATT_SMEM_B>>>();
    }

    // 3) output projection
    {
        dim3 grid(CC / 128, (BB * TT) / 128);      // (8, 32)
        hgemm3_nt<<<grid, 256, GSMEM_B>>>((const __nv_bfloat16*)atts,
                                          (const __nv_bfloat16*)wps, out, 0);
    }
}

// round 10
// speedup vs baseline: 2.5481x; 1.0061x over previous
#include <cuda_runtime.h>
#include <cuda_bf16.h>
#include <math.h>
#include <cstdint>

#define BB 2
#define TT 2048
#define CC 1024
#define HH 16
#define DKK 64
#define K2 2048   // [hi | lo] compact layout

// bf16 scratch
__device__ __nv_bfloat16 g_qh[(size_t)BB*HH*TT*DKK];
__device__ __nv_bfloat16 g_ql[(size_t)BB*HH*TT*DKK];
__device__ __nv_bfloat16 g_kh[(size_t)BB*HH*TT*DKK];
__device__ __nv_bfloat16 g_kl[(size_t)BB*HH*TT*DKK];
__device__ __nv_bfloat16 g_vth[(size_t)BB*HH*DKK*TT];  // V^T [b,h,d,t]
__device__ __nv_bfloat16 g_vtl[(size_t)BB*HH*DKK*TT];
__device__ __nv_bfloat16 g_xs[(size_t)BB*TT*K2];       // x'      [4096, 2048]
__device__ __nv_bfloat16 g_was[(size_t)3*CC*K2];       // w_attn' [3072, 2048]
__device__ __nv_bfloat16 g_wps[(size_t)CC*K2];         // w_proj' [1024, 2048]
__device__ __nv_bfloat16 g_atts[(size_t)BB*TT*K2];     // att'    [4096, 2048]

__device__ __forceinline__ uint32_t smem_u32(const void* p) {
    uint32_t a;
    asm("{ .reg .u64 t; cvta.to.shared.u64 t, %1; cvt.u32.u64 %0, t; }" : "=r"(a) : "l"(p));
    return a;
}

__device__ __forceinline__ uint32_t pack_bf16(float a, float b) {
    uint32_t r;
    asm("cvt.rn.bf16x2.f32 %0, %1, %2;" : "=r"(r) : "f"(b), "f"(a));
    return r;
}
__device__ __forceinline__ float bf16lo_f(uint32_t r) { return __uint_as_float(r << 16); }
__device__ __forceinline__ float bf16hi_f(uint32_t r) { return __uint_as_float(r & 0xFFFF0000u); }

#define MMA16816(d, a0,a1,a2,a3, b0,b1) \
    asm volatile("mma.sync.aligned.m16n8k16.row.col.f32.bf16.bf16.f32 " \
        "{%0,%1,%2,%3}, {%4,%5,%6,%7}, {%8,%9}, {%0,%1,%2,%3};" \
        : "+f"((d)[0]), "+f"((d)[1]), "+f"((d)[2]), "+f"((d)[3]) \
        : "r"(a0), "r"(a1), "r"(a2), "r"(a3), "r"(b0), "r"(b1))

#define LDSM4(r0,r1,r2,r3, addr) \
    asm volatile("ldmatrix.sync.aligned.m8n8.x4.shared.b16 {%0,%1,%2,%3}, [%4];" \
        : "=r"(r0), "=r"(r1), "=r"(r2), "=r"(r3) : "r"(addr))

#define CPA16(dst, src) \
    asm volatile("cp.async.cg.shared.global [%0], [%1], 16;" :: "r"(dst), "l"(src))

// ---------------------------------------------------------------------------
// split: fp32 [R,1024] -> bf16 [R,2048] = [hi | lo]
// ---------------------------------------------------------------------------
__global__ __launch_bounds__(256) void split_kernel(const float* __restrict__ in,
                                                    __nv_bfloat16* __restrict__ out,
                                                    int n)
{
    int i4 = (blockIdx.x * 256 + threadIdx.x) * 4;
    if (i4 >= n) return;
    float4 v = *(const float4*)(in + i4);
    int r = i4 >> 10;
    int c = i4 & 1023;
    __nv_bfloat16 h0 = __float2bfloat16(v.x);
    __nv_bfloat16 h1 = __float2bfloat16(v.y);
    __nv_bfloat16 h2 = __float2bfloat16(v.z);
    __nv_bfloat16 h3 = __float2bfloat16(v.w);
    __nv_bfloat16 l0 = __float2bfloat16(v.x - __bfloat162float(h0));
    __nv_bfloat16 l1 = __float2bfloat16(v.y - __bfloat162float(h1));
    __nv_bfloat16 l2 = __float2bfloat16(v.z - __bfloat162float(h2));
    __nv_bfloat16 l3 = __float2bfloat16(v.w - __bfloat162float(h3));
    __nv_bfloat162* ph = (__nv_bfloat162*)(out + (size_t)r * K2 + c);
    __nv_bfloat162* pl = (__nv_bfloat162*)(out + (size_t)r * K2 + 1024 + c);
    ph[0] = __nv_bfloat162(h0, h1); ph[1] = __nv_bfloat162(h2, h3);
    pl[0] = __nv_bfloat162(l0, l1); pl[1] = __nv_bfloat162(l2, l3);
}

// ---------------------------------------------------------------------------
// 3-term bf16 GEMM NT: C = Ah*Bh^T + Al*Bh^T + Ah*Bl^T over base K=1024.
// Separated MMA passes for acc reuse distance; bl loaded lazily in pass 3
// to bound register pressure (peak operands: ah16+al16+bh8 = 40 regs).
// ---------------------------------------------------------------------------
#define RS 40
#define NCHUNK 32
#define TILE_E (128 * RS)
#define TILE_B (TILE_E * 2)
#define STAGE_E (4 * TILE_E)
#define STAGE_B (4 * TILE_B)
#define GSMEM_B (2 * STAGE_B)

__global__ __launch_bounds__(256, 2) void hgemm3_nt(const __nv_bfloat16* __restrict__ A,
                                                    const __nv_bfloat16* __restrict__ Bw,
                                                    float* __restrict__ Cout,
                                                    int mode)
{
    extern __shared__ __align__(16) __nv_bfloat16 sm3[];
    const uint32_t sbase = smem_u32(sm3);

    const int tid  = threadIdx.x;
    const int lane = tid & 31;
    const int warp = tid >> 5;
    const int wm   = warp & 1;
    const int wn   = warp >> 1;
    const int bm   = blockIdx.y * 128;
    const int bn   = blockIdx.x * 128;

    const int r0 = tid >> 2, o = tid & 3;
    const uint32_t e0b = (uint32_t)(r0 * RS + o * 8) * 2;
    const uint32_t e1b = (uint32_t)((r0 + 64) * RS + o * 8) * 2;

    const __nv_bfloat16* Ag = A  + (size_t)bm * K2;
    const __nv_bfloat16* Bg = Bw + (size_t)bn * K2;
    const __nv_bfloat16* a0p = Ag + (size_t)r0 * K2 + o * 8;
    const __nv_bfloat16* a1p = Ag + (size_t)(r0 + 64) * K2 + o * 8;
    const __nv_bfloat16* b0p = Bg + (size_t)r0 * K2 + o * 8;
    const __nv_bfloat16* b1p = Bg + (size_t)(r0 + 64) * K2 + o * 8;

#define ISSUE3(buf, ch) do {                                                   \
    const int ko = (ch) * 32;                                                  \
    const uint32_t base = sbase + (buf) * STAGE_B;                             \
    CPA16(base + e0b,              a0p + ko);                                  \
    CPA16(base + e1b,              a1p + ko);                                  \
    CPA16(base + TILE_B + e0b,     a0p + ko + 1024);                           \
    CPA16(base + TILE_B + e1b,     a1p + ko + 1024);                           \
    CPA16(base + 2*TILE_B + e0b,   b0p + ko);                                  \
    CPA16(base + 2*TILE_B + e1b,   b1p + ko);                                  \
    CPA16(base + 3*TILE_B + e0b,   b0p + ko + 1024);                           \
    CPA16(base + 3*TILE_B + e1b,   b1p + ko + 1024);                           \
    asm volatile("cp.async.commit_group;");                                    \
} while (0)

    ISSUE3(0, 0);
    ISSUE3(1, 1);

    float acc[4][4][4];
#pragma unroll
    for (int mi = 0; mi < 4; mi++)
#pragma unroll
        for (int ni = 0; ni < 4; ni++)
#pragma unroll
            for (int r = 0; r < 4; r++) acc[mi][ni][r] = 0.f;

    const int arow  = wm * 64 + (lane & 15);
    const int acol8 = (lane >> 4) * 8;
    const int brow  = (lane & 7) + ((lane & 16) ? 8 : 0);
    const int bcol8 = (lane & 8) ? 8 : 0;

    for (int c = 0; c < NCHUNK; c++) {
        const int buf = c & 1;
        if (c + 1 < NCHUNK) asm volatile("cp.async.wait_group 1;");
        else                asm volatile("cp.async.wait_group 0;");
        __syncthreads();

        const __nv_bfloat16* sAh = sm3 + buf * STAGE_E;
        const __nv_bfloat16* sAl = sAh + TILE_E;
        const __nv_bfloat16* sBh = sAh + 2 * TILE_E;
        const __nv_bfloat16* sBl = sAh + 3 * TILE_E;

#pragma unroll
        for (int kk = 0; kk < 2; kk++) {
            uint32_t ah[4][4], al[4][4], bh[2][4];
#pragma unroll
            for (int mi = 0; mi < 4; mi++) {
                uint32_t addr = smem_u32(&sAh[(arow + mi * 16) * RS + kk * 16 + acol8]);
                LDSM4(ah[mi][0], ah[mi][1], ah[mi][2], ah[mi][3], addr);
            }
#pragma unroll
            for (int mi = 0; mi < 4; mi++) {
                uint32_t addr = smem_u32(&sAl[(arow + mi * 16) * RS + kk * 16 + acol8]);
                LDSM4(al[mi][0], al[mi][1], al[mi][2], al[mi][3], addr);
            }
#pragma unroll
            for (int np = 0; np < 2; np++) {
                uint32_t addr = smem_u32(&sBh[(wn * 32 + np * 16 + brow) * RS
                                              + kk * 16 + bcol8]);
                LDSM4(bh[np][0], bh[np][1], bh[np][2], bh[np][3], addr);
            }
            // pass 1: hi*hi — 16 MMAs, all distinct accumulators
#pragma unroll
            for (int mi = 0; mi < 4; mi++)
#pragma unroll
                for (int np = 0; np < 2; np++) {
                    MMA16816(acc[mi][2*np],   ah[mi][0], ah[mi][1], ah[mi][2], ah[mi][3],
                             bh[np][0], bh[np][1]);
                    MMA16816(acc[mi][2*np+1], ah[mi][0], ah[mi][1], ah[mi][2], ah[mi][3],
                             bh[np][2], bh[np][3]);
                }
            // pass 2: lo*hi — 16 MMAs (reuse distance 16)
#pragma unroll
            for (int mi = 0; mi < 4; mi++)
#pragma unroll
                for (int np = 0; np < 2; np++) {
                    MMA16816(acc[mi][2*np],   al[mi][0], al[mi][1], al[mi][2], al[mi][3],
                             bh[np][0], bh[np][1]);
                    MMA16816(acc[mi][2*np+1], al[mi][0], al[mi][1], al[mi][2], al[mi][3],
                             bh[np][2], bh[np][3]);
                }
            // pass 3: hi*lo — bl loaded lazily (reuses bh's registers)
#pragma unroll
            for (int np = 0; np < 2; np++) {
                uint32_t bl[4];
                uint32_t addr = smem_u32(&sBl[(wn * 32 + np * 16 + brow) * RS
                                              + kk * 16 + bcol8]);
                LDSM4(bl[0], bl[1], bl[2], bl[3], addr);
#pragma unroll
                for (int mi = 0; mi < 4; mi++) {
                    MMA16816(acc[mi][2*np],   ah[mi][0], ah[mi][1], ah[mi][2], ah[mi][3],
                             bl[0], bl[1]);
                    MMA16816(acc[mi][2*np+1], ah[mi][0], ah[mi][1], ah[mi][2], ah[mi][3],
                             bl[2], bl[3]);
                }
            }
        }

        __syncthreads();
        if (c + 2 < NCHUNK) ISSUE3(buf, c + 2);
    }

    const int gid = lane >> 2;
    const int tig = lane & 3;
    if (mode == 0) {
#pragma unroll
        for (int mi = 0; mi < 4; mi++) {
            const int m0 = bm + wm * 64 + mi * 16 + gid;
#pragma unroll
            for (int ni = 0; ni < 4; ni++) {
                const int n0 = bn + wn * 32 + ni * 8 + tig * 2;
                *(float2*)(Cout + (size_t)m0 * 1024 + n0) =
                    make_float2(acc[mi][ni][0], acc[mi][ni][1]);
                *(float2*)(Cout + (size_t)(m0 + 8) * 1024 + n0) =
                    make_float2(acc[mi][ni][2], acc[mi][ni][3]);
            }
        }
    } else {
#pragma unroll
        for (int mi = 0; mi < 4; mi++) {
            const int m0 = bm + wm * 64 + mi * 16 + gid;
#pragma unroll
            for (int ni = 0; ni < 4; ni++) {
                const int n0 = bn + wn * 32 + ni * 8 + tig * 2;
                const int which = n0 >> 10;
                const int rem = n0 & 1023;
                const int h = rem >> 6;
                const int d = rem & 63;
#pragma unroll
                for (int half = 0; half < 2; half++) {
                    const int m = m0 + half * 8;
                    const int b = m >> 11;
                    const int t = m & 2047;
                    const size_t bh_ = (size_t)(b * HH + h);
                    float v0 = acc[mi][ni][2 * half];
                    float v1 = acc[mi][ni][2 * half + 1];
                    uint32_t hi2 = pack_bf16(v0, v1);
                    float lo0 = v0 - bf16lo_f(hi2);
                    float lo1 = v1 - bf16hi_f(hi2);
                    uint32_t lo2 = pack_bf16(lo0, lo1);
                    if (which == 2) {
                        const size_t base = bh_ * DKK * TT + (size_t)t;
                        g_vth[base + (size_t)d * TT]       = __float2bfloat16(v0);
                        g_vth[base + (size_t)(d + 1) * TT] = __float2bfloat16(v1);
                        g_vtl[base + (size_t)d * TT]       = __float2bfloat16(lo0);
                        g_vtl[base + (size_t)(d + 1) * TT] = __float2bfloat16(lo1);
                    } else {
                        const size_t off = bh_ * TT * DKK + (size_t)t * DKK + d;
                        __nv_bfloat16* ph = (which == 0) ? g_qh : g_kh;
                        __nv_bfloat16* pl = (which == 0) ? g_ql : g_kl;
                        *(uint32_t*)(ph + off) = hi2;
                        *(uint32_t*)(pl + off) = lo2;
                    }
                }
            }
        }
    }
}

// ---------------------------------------------------------------------------
// Tensor-core flash attention, causal; separated MMA passes (lazy lo loads).
// ---------------------------------------------------------------------------
#define QTILE 128
#define KTILE 64
#define ARS 72
#define QELEMS (QTILE * ARS)
#define KTELEMS (KTILE * ARS)
#define STG0 (2 * QELEMS)
#define STG_STRIDE (4 * KTELEMS)
#define ATT_SMEM_B ((STG0 + 2 * STG_STRIDE) * 2)

__global__ __launch_bounds__(256) void attn_mma()
{
    extern __shared__ __align__(16) __nv_bfloat16 sm[];

    const int tid  = threadIdx.x;
    const int lane = tid & 31;
    const int w    = tid >> 5;
    const int qt   = gridDim.x - 1 - blockIdx.x;
    const int h    = blockIdx.y;
    const int b    = blockIdx.z;
    const int q0   = qt * QTILE;
    const size_t bh = (size_t)(b * HH + h);
    const int njt  = 2 * qt + 2;

    const __nv_bfloat16* Qh = g_qh + bh * TT * DKK;
    const __nv_bfloat16* Ql = g_ql + bh * TT * DKK;
    const __nv_bfloat16* Kh = g_kh + bh * TT * DKK;
    const __nv_bfloat16* Kl = g_kl + bh * TT * DKK;
    const __nv_bfloat16* Vh = g_vth + bh * DKK * TT;
    const __nv_bfloat16* Vl = g_vtl + bh * DKK * TT;

#pragma unroll
    for (int i = 0; i < 8; i++) {
        int lin = tid + i * 256;
        int arr = lin >> 10;
        int r   = (lin & 1023) >> 3;
        int ch  = lin & 7;
        const __nv_bfloat16* src = (arr ? Ql : Qh) + (size_t)(q0 + r) * DKK + ch * 8;
        uint32_t dst = smem_u32(&sm[arr * QELEMS + r * ARS + ch * 8]);
        CPA16(dst, src);
    }

    const int lr = tid >> 3, lch = tid & 7;
#define ISSUE_KV(jt, s) do {                                                      \
    int k0_ = (jt) * KTILE;                                                       \
    __nv_bfloat16* base = sm + STG0 + (s) * STG_STRIDE;                           \
    CPA16(smem_u32(&base[lr * ARS + lch * 8]),                                    \
          Kh + (size_t)(k0_ + lr) * DKK + lch * 8);                               \
    CPA16(smem_u32(&base[(lr + 32) * ARS + lch * 8]),                             \
          Kh + (size_t)(k0_ + lr + 32) * DKK + lch * 8);                          \
    CPA16(smem_u32(&base[KTELEMS + lr * ARS + lch * 8]),                          \
          Kl + (size_t)(k0_ + lr) * DKK + lch * 8);                               \
    CPA16(smem_u32(&base[KTELEMS + (lr + 32) * ARS + lch * 8]),                   \
          Kl + (size_t)(k0_ + lr + 32) * DKK + lch * 8);                          \
    CPA16(smem_u32(&base[2 * KTELEMS + lr * ARS + lch * 8]),                      \
          Vh + (size_t)lr * TT + k0_ + lch * 8);                                  \
    CPA16(smem_u32(&base[2 * KTELEMS + (lr + 32) * ARS + lch * 8]),               \
          Vh + (size_t)(lr + 32) * TT + k0_ + lch * 8);                           \
    CPA16(smem_u32(&base[3 * KTELEMS + lr * ARS + lch * 8]),                      \
          Vl + (size_t)lr * TT + k0_ + lch * 8);                                  \
    CPA16(smem_u32(&base[3 * KTELEMS + (lr + 32) * ARS + lch * 8]),               \
          Vl + (size_t)(lr + 32) * TT + k0_ + lch * 8);                           \
    asm volatile("cp.async.commit_group;");                                       \
} while (0)

    ISSUE_KV(0, 0);
    ISSUE_KV(1, 1);

    float oacc[8][4];
#pragma unroll
    for (int ni = 0; ni < 8; ni++)
#pragma unroll
        for (int r = 0; r < 4; r++) oacc[ni][r] = 0.f;
    float mrow[2] = {-1e30f, -1e30f};
    float lrow[2] = {0.f, 0.f};

    uint32_t ah[4][4];
    bool ah_loaded = false;

    const int arow = w * 16 + (lane & 15);
    const int acol8 = (lane >> 4) * 8;
    const int brow = (lane & 7) + ((lane & 16) ? 8 : 0);
    const int bcol8 = (lane & 8) ? 8 : 0;
    const int rr = lane >> 2;
    const int cc2 = (lane & 3) * 2;

    for (int jt = 0; jt < njt; jt++) {
        const int s = jt & 1;
        if (jt + 1 < njt) asm volatile("cp.async.wait_group 1;");
        else              asm volatile("cp.async.wait_group 0;");
        __syncthreads();

        __nv_bfloat16* sKh = sm + STG0 + s * STG_STRIDE;
        __nv_bfloat16* sKl = sKh + KTELEMS;
        __nv_bfloat16* sVh = sKh + 2 * KTELEMS;
        __nv_bfloat16* sVl = sKh + 3 * KTELEMS;

        if (!ah_loaded) {
            ah_loaded = true;
#pragma unroll
            for (int kk = 0; kk < 4; kk++) {
                uint32_t addr = smem_u32(&sm[arow * ARS + kk * 16 + acol8]);
                LDSM4(ah[kk][0], ah[kk][1], ah[kk][2], ah[kk][3], addr);
            }
        }

        float sacc[8][4];
#pragma unroll
        for (int ni = 0; ni < 8; ni++)
#pragma unroll
            for (int r = 0; r < 4; r++) sacc[ni][r] = 0.f;

#pragma unroll
        for (int kk = 0; kk < 4; kk++) {
            uint32_t al4[4];
            {
                uint32_t addr = smem_u32(&sm[QELEMS + arow * ARS + kk * 16 + acol8]);
                LDSM4(al4[0], al4[1], al4[2], al4[3], addr);
            }
            uint32_t bh4[4][4];
#pragma unroll
            for (int np = 0; np < 4; np++) {
                uint32_t addr = smem_u32(&sKh[(np * 16 + brow) * ARS + kk * 16 + bcol8]);
                LDSM4(bh4[np][0], bh4[np][1], bh4[np][2], bh4[np][3], addr);
            }
            // pass 1: Qh*Kh
#pragma unroll
            for (int np = 0; np < 4; np++) {
                MMA16816(sacc[2*np],   ah[kk][0], ah[kk][1], ah[kk][2], ah[kk][3],
                         bh4[np][0], bh4[np][1]);
                MMA16816(sacc[2*np+1], ah[kk][0], ah[kk][1], ah[kk][2], ah[kk][3],
                         bh4[np][2], bh4[np][3]);
            }
            // pass 2: Ql*Kh
#pragma unroll
            for (int np = 0; np < 4; np++) {
                MMA16816(sacc[2*np],   al4[0], al4[1], al4[2], al4[3],
                         bh4[np][0], bh4[np][1]);
                MMA16816(sacc[2*np+1], al4[0], al4[1], al4[2], al4[3],
                         bh4[np][2], bh4[np][3]);
            }
            // pass 3: Qh*Kl (lazy loads)
#pragma unroll
            for (int np = 0; np < 4; np++) {
                uint32_t bl4[4];
                uint32_t addr = smem_u32(&sKl[(np * 16 + brow) * ARS + kk * 16 + bcol8]);
                LDSM4(bl4[0], bl4[1], bl4[2], bl4[3], addr);
                MMA16816(sacc[2*np],   ah[kk][0], ah[kk][1], ah[kk][2], ah[kk][3],
                         bl4[0], bl4[1]);
                MMA16816(sacc[2*np+1], ah[kk][0], ah[kk][1], ah[kk][2], ah[kk][3],
                         bl4[2], bl4[3]);
            }
        }

        const int k0 = jt * KTILE;
        const int r0 = q0 + w * 16 + rr;
        const int r1 = r0 + 8;
        const bool need_mask = (k0 + KTILE - 1 > r0);
#pragma unroll
        for (int ni = 0; ni < 8; ni++) {
            const int col = k0 + ni * 8 + cc2;
#pragma unroll
            for (int c = 0; c < 2; c++) {
                sacc[ni][c]     *= 0.125f;
                sacc[ni][2 + c] *= 0.125f;
                if (need_mask) {
                    if (col + c > r0) sacc[ni][c]     = -1e30f;
                    if (col + c > r1) sacc[ni][2 + c] = -1e30f;
                }
            }
        }

        float mx0 = -1e30f, mx1 = -1e30f;
#pragma unroll
        for (int ni = 0; ni < 8; ni++) {
            mx0 = fmaxf(mx0, fmaxf(sacc[ni][0], sacc[ni][1]));
            mx1 = fmaxf(mx1, fmaxf(sacc[ni][2], sacc[ni][3]));
        }
        mx0 = fmaxf(mx0, __shfl_xor_sync(0xffffffffu, mx0, 1));
        mx0 = fmaxf(mx0, __shfl_xor_sync(0xffffffffu, mx0, 2));
        mx1 = fmaxf(mx1, __shfl_xor_sync(0xffffffffu, mx1, 1));
        mx1 = fmaxf(mx1, __shfl_xor_sync(0xffffffffu, mx1, 2));
        const float mn0 = fmaxf(mrow[0], mx0);
        const float mn1 = fmaxf(mrow[1], mx1);
        const float al0 = __expf(mrow[0] - mn0);
        const float al1 = __expf(mrow[1] - mn1);
        mrow[0] = mn0; mrow[1] = mn1;
        float sum0 = 0.f, sum1 = 0.f;
#pragma unroll
        for (int ni = 0; ni < 8; ni++) {
            sacc[ni][0] = __expf(sacc[ni][0] - mn0); sum0 += sacc[ni][0];
            sacc[ni][1] = __expf(sacc[ni][1] - mn0); sum0 += sacc[ni][1];
            sacc[ni][2] = __expf(sacc[ni][2] - mn1); sum1 += sacc[ni][2];
            sacc[ni][3] = __expf(sacc[ni][3] - mn1); sum1 += sacc[ni][3];
        }
        sum0 += __shfl_xor_sync(0xffffffffu, sum0, 1);
        sum0 += __shfl_xor_sync(0xffffffffu, sum0, 2);
        sum1 += __shfl_xor_sync(0xffffffffu, sum1, 1);
        sum1 += __shfl_xor_sync(0xffffffffu, sum1, 2);
        lrow[0] = lrow[0] * al0 + sum0;
        lrow[1] = lrow[1] * al1 + sum1;
#pragma unroll
        for (int ni = 0; ni < 8; ni++) {
            oacc[ni][0] *= al0; oacc[ni][1] *= al0;
            oacc[ni][2] *= al1; oacc[ni][3] *= al1;
        }

#pragma unroll
        for (int kk = 0; kk < 4; kk++) {
            const int b2 = 2 * kk, b3 = 2 * kk + 1;
            uint32_t pah[4], pal[4];
            pah[0] = pack_bf16(sacc[b2][0], sacc[b2][1]);
            pah[1] = pack_bf16(sacc[b2][2], sacc[b2][3]);
            pah[2] = pack_bf16(sacc[b3][0], sacc[b3][1]);
            pah[3] = pack_bf16(sacc[b3][2], sacc[b3][3]);
            pal[0] = pack_bf16(sacc[b2][0] - bf16lo_f(pah[0]), sacc[b2][1] - bf16hi_f(pah[0]));
            pal[1] = pack_bf16(sacc[b2][2] - bf16lo_f(pah[1]), sacc[b2][3] - bf16hi_f(pah[1]));
            pal[2] = pack_bf16(sacc[b3][0] - bf16lo_f(pah[2]), sacc[b3][1] - bf16hi_f(pah[2]));
            pal[3] = pack_bf16(sacc[b3][2] - bf16lo_f(pah[3]), sacc[b3][3] - bf16hi_f(pah[3]));
            uint32_t vh4[4][4];
#pragma unroll
            for (int dp = 0; dp < 4; dp++) {
                uint32_t addr = smem_u32(&sVh[(dp * 16 + brow) * ARS + kk * 16 + bcol8]);
                LDSM4(vh4[dp][0], vh4[dp][1], vh4[dp][2], vh4[dp][3], addr);
            }
            // pass 1: Ph*Vh
#pragma unroll
            for (int dp = 0; dp < 4; dp++) {
                MMA16816(oacc[2*dp],   pah[0], pah[1], pah[2], pah[3],
                         vh4[dp][0], vh4[dp][1]);
                MMA16816(oacc[2*dp+1], pah[0], pah[1], pah[2], pah[3],
                         vh4[dp][2], vh4[dp][3]);
            }
            // pass 2: Pl*Vh
#pragma unroll
            for (int dp = 0; dp < 4; dp++) {
                MMA16816(oacc[2*dp],   pal[0], pal[1], pal[2], pal[3],
                         vh4[dp][0], vh4[dp][1]);
                MMA16816(oacc[2*dp+1], pal[0], pal[1], pal[2], pal[3],
                         vh4[dp][2], vh4[dp][3]);
            }
            // pass 3: Ph*Vl (lazy loads)
#pragma unroll
            for (int dp = 0; dp < 4; dp++) {
                uint32_t vl4[4];
                uint32_t addr = smem_u32(&sVl[(dp * 16 + brow) * ARS + kk * 16 + bcol8]);
                LDSM4(vl4[0], vl4[1], vl4[2], vl4[3], addr);
                MMA16816(oacc[2*dp],   pah[0], pah[1], pah[2], pah[3], vl4[0], vl4[1]);
                MMA16816(oacc[2*dp+1], pah[0], pah[1], pah[2], pah[3], vl4[2], vl4[3]);
            }
        }

        __syncthreads();
        if (jt + 2 < njt) ISSUE_KV(jt + 2, s);
    }

    // epilogue: normalize, hi/lo split, write g_atts [hi | lo]
    const float inv0 = 1.f / lrow[0];
    const float inv1 = 1.f / lrow[1];
    const int row0 = q0 + w * 16 + rr;
    const size_t m0 = (size_t)b * TT + row0;
    __nv_bfloat16* dst0 = g_atts + m0 * K2 + h * 64;
    __nv_bfloat16* dst1 = g_atts + (m0 + 8) * K2 + h * 64;
#pragma unroll
    for (int ni = 0; ni < 8; ni++) {
        const int d = ni * 8 + cc2;
        float v0 = oacc[ni][0] * inv0, v1 = oacc[ni][1] * inv0;
        float v2 = oacc[ni][2] * inv1, v3 = oacc[ni][3] * inv1;
        uint32_t h0 = pack_bf16(v0, v1);
        uint32_t l0 = pack_bf16(v0 - bf16lo_f(h0), v1 - bf16hi_f(h0));
        uint32_t h1 = pack_bf16(v2, v3);
        uint32_t l1 = pack_bf16(v2 - bf16lo_f(h1), v3 - bf16hi_f(h1));
        *(uint32_t*)(dst0 + d)        = h0;
        *(uint32_t*)(dst0 + 1024 + d) = l0;
        *(uint32_t*)(dst1 + d)        = h1;
        *(uint32_t*)(dst1 + 1024 + d) = l1;
    }
}

// ---------------------------------------------------------------------------
extern "C" void kernel_launch(void* const* d_in, const int* in_sizes, int n_in,
                              void* d_out, int out_size)
{
    const float* x      = (const float*)d_in[0];   // [2, 2048, 1024]
    const float* w_attn = (const float*)d_in[1];   // [3072, 1024]
    const float* w_proj = (const float*)d_in[2];   // [1024, 1024]
    float* out = (float*)d_out;                    // [2, 2048, 1024]

    cudaFuncSetAttribute(hgemm3_nt,
                         cudaFuncAttributeMaxDynamicSharedMemorySize, GSMEM_B);
    cudaFuncSetAttribute(attn_mma,
                         cudaFuncAttributeMaxDynamicSharedMemorySize, ATT_SMEM_B);

    void *xs, *was, *wps, *atts;
    cudaGetSymbolAddress(&xs,   g_xs);
    cudaGetSymbolAddress(&was,  g_was);
    cudaGetSymbolAddress(&wps,  g_wps);
    cudaGetSymbolAddress(&atts, g_atts);

    // 0) [hi|lo] splits of the fp32 inputs
    split_kernel<<<(BB*TT*CC/4 + 255)/256, 256>>>(x,      (__nv_bfloat16*)xs,  BB*TT*CC);
    split_kernel<<<(3*CC*CC/4  + 255)/256, 256>>>(w_attn, (__nv_bfloat16*)was, 3*CC*CC);
    split_kernel<<<(CC*CC/4    + 255)/256, 256>>>(w_proj, (__nv_bfloat16*)wps, CC*CC);

    // 1) QKV projection (3-term bf16 GEMM) -> bf16 hi/lo per-head (V transposed)
    {
        dim3 grid(3 * CC / 128, (BB * TT) / 128);  // (24, 32)
        hgemm3_nt<<<grid, 256, GSMEM_B>>>((const __nv_bfloat16*)xs,
                                          (const __nv_bfloat16*)was, nullptr, 1);
    }

    // 2) causal flash attention on tensor cores -> g_atts [hi|lo]
    {
        dim3 grid(TT / QTILE, HH, BB);             // (16, 16, 2)
        attn_mma<<<grid, 256, ATT_SMEM_B>>>();
    }

    // 3) output projection
    {
        dim3 grid(CC / 128, (BB * TT) / 128);      // (8, 32)
        hgemm3_nt<<<grid, 256, GSMEM_B>>>((const __nv_bfloat16*)atts,
                                          (const __nv_bfloat16*)wps, out, 0);
    }
}

// round 11
// speedup vs baseline: 2.6058x; 1.0226x over previous
#include <cuda_runtime.h>
#include <cuda_bf16.h>
#include <cuda_fp16.h>
#include <math.h>
#include <cstdint>

#define BB 2
#define TT 2048
#define CC 1024
#define HH 16
#define DKK 64
#define K2 2048   // [hi | lo] compact layout

// bf16 scratch (QKV path)
__device__ __nv_bfloat16 g_qh[(size_t)BB*HH*TT*DKK];
__device__ __nv_bfloat16 g_ql[(size_t)BB*HH*TT*DKK];
__device__ __nv_bfloat16 g_kh[(size_t)BB*HH*TT*DKK];
__device__ __nv_bfloat16 g_kl[(size_t)BB*HH*TT*DKK];
__device__ __nv_bfloat16 g_vth[(size_t)BB*HH*DKK*TT];  // V^T [b,h,d,t]
__device__ __nv_bfloat16 g_vtl[(size_t)BB*HH*DKK*TT];
__device__ __nv_bfloat16 g_xs[(size_t)BB*TT*K2];       // x'      [4096, 2048]
__device__ __nv_bfloat16 g_was[(size_t)3*CC*K2];       // w_attn' [3072, 2048]
// fp16 scratch (proj path)
__device__ __half g_att16[(size_t)BB*TT*K2];           // O  [4096, 2048] = [Oh|Ol]
__device__ __half g_wp16[(size_t)CC*K2];               // W' [1024, 2048] = [Wh|Wh]

__device__ __forceinline__ uint32_t smem_u32(const void* p) {
    uint32_t a;
    asm("{ .reg .u64 t; cvta.to.shared.u64 t, %1; cvt.u32.u64 %0, t; }" : "=r"(a) : "l"(p));
    return a;
}

__device__ __forceinline__ uint32_t pack_bf16(float a, float b) {
    uint32_t r;
    asm("cvt.rn.bf16x2.f32 %0, %1, %2;" : "=r"(r) : "f"(b), "f"(a));
    return r;
}
__device__ __forceinline__ float bf16lo_f(uint32_t r) { return __uint_as_float(r << 16); }
__device__ __forceinline__ float bf16hi_f(uint32_t r) { return __uint_as_float(r & 0xFFFF0000u); }

__device__ __forceinline__ uint32_t pack_f16(float a, float b) {
    __half2 h = __floats2half2_rn(a, b);   // a -> low, b -> high
    return *(uint32_t*)&h;
}

#define MMA16816(d, a0,a1,a2,a3, b0,b1) \
    asm volatile("mma.sync.aligned.m16n8k16.row.col.f32.bf16.bf16.f32 " \
        "{%0,%1,%2,%3}, {%4,%5,%6,%7}, {%8,%9}, {%0,%1,%2,%3};" \
        : "+f"((d)[0]), "+f"((d)[1]), "+f"((d)[2]), "+f"((d)[3]) \
        : "r"(a0), "r"(a1), "r"(a2), "r"(a3), "r"(b0), "r"(b1))

#define MMA16816H(d, a0,a1,a2,a3, b0,b1) \
    asm volatile("mma.sync.aligned.m16n8k16.row.col.f32.f16.f16.f32 " \
        "{%0,%1,%2,%3}, {%4,%5,%6,%7}, {%8,%9}, {%0,%1,%2,%3};" \
        : "+f"((d)[0]), "+f"((d)[1]), "+f"((d)[2]), "+f"((d)[3]) \
        : "r"(a0), "r"(a1), "r"(a2), "r"(a3), "r"(b0), "r"(b1))

#define LDSM4(r0,r1,r2,r3, addr) \
    asm volatile("ldmatrix.sync.aligned.m8n8.x4.shared.b16 {%0,%1,%2,%3}, [%4];" \
        : "=r"(r0), "=r"(r1), "=r"(r2), "=r"(r3) : "r"(addr))

#define LDSM2(r0,r1, addr) \
    asm volatile("ldmatrix.sync.aligned.m8n8.x2.shared.b16 {%0,%1}, [%2];" \
        : "=r"(r0), "=r"(r1) : "r"(addr))

#define CPA16(dst, src) \
    asm volatile("cp.async.cg.shared.global [%0], [%1], 16;" :: "r"(dst), "l"(src))

// ---------------------------------------------------------------------------
// split: fp32 [R,1024] -> bf16 [R,2048] = [hi | lo]   (QKV operands)
// ---------------------------------------------------------------------------
__global__ __launch_bounds__(256) void split_kernel(const float* __restrict__ in,
                                                    __nv_bfloat16* __restrict__ out,
                                                    int n)
{
    int i4 = (blockIdx.x * 256 + threadIdx.x) * 4;
    if (i4 >= n) return;
    float4 v = *(const float4*)(in + i4);
    int r = i4 >> 10;
    int c = i4 & 1023;
    __nv_bfloat16 h0 = __float2bfloat16(v.x);
    __nv_bfloat16 h1 = __float2bfloat16(v.y);
    __nv_bfloat16 h2 = __float2bfloat16(v.z);
    __nv_bfloat16 h3 = __float2bfloat16(v.w);
    __nv_bfloat16 l0 = __float2bfloat16(v.x - __bfloat162float(h0));
    __nv_bfloat16 l1 = __float2bfloat16(v.y - __bfloat162float(h1));
    __nv_bfloat16 l2 = __float2bfloat16(v.z - __bfloat162float(h2));
    __nv_bfloat16 l3 = __float2bfloat16(v.w - __bfloat162float(h3));
    __nv_bfloat162* ph = (__nv_bfloat162*)(out + (size_t)r * K2 + c);
    __nv_bfloat162* pl = (__nv_bfloat162*)(out + (size_t)r * K2 + 1024 + c);
    ph[0] = __nv_bfloat162(h0, h1); ph[1] = __nv_bfloat162(h2, h3);
    pl[0] = __nv_bfloat162(l0, l1); pl[1] = __nv_bfloat162(l2, l3);
}

// ---------------------------------------------------------------------------
// split_w16: fp32 W [1024,1024] -> fp16 [1024,2048] = [Wh | Wh] (duplicated)
// ---------------------------------------------------------------------------
__global__ __launch_bounds__(256) void split_w16(const float* __restrict__ in,
                                                 __half* __restrict__ out, int n)
{
    int i4 = (blockIdx.x * 256 + threadIdx.x) * 4;
    if (i4 >= n) return;
    float4 v = *(const float4*)(in + i4);
    int r = i4 >> 10;
    int c = i4 & 1023;
    uint32_t p0 = pack_f16(v.x, v.y);
    uint32_t p1 = pack_f16(v.z, v.w);
    uint32_t* d0 = (uint32_t*)(out + (size_t)r * K2 + c);
    uint32_t* d1 = (uint32_t*)(out + (size_t)r * K2 + 1024 + c);
    d0[0] = p0; d0[1] = p1;
    d1[0] = p0; d1[1] = p1;
}

// ---------------------------------------------------------------------------
// 3-term bf16 GEMM NT (QKV): C = Ah*Bh^T + Al*Bh^T + Ah*Bl^T, base K=1024.
// (verified R10 structure)
// ---------------------------------------------------------------------------
#define RS 40
#define NCHUNK 32
#define TILE_E (128 * RS)
#define TILE_B (TILE_E * 2)
#define STAGE_E (4 * TILE_E)
#define STAGE_B (4 * TILE_B)
#define GSMEM_B (2 * STAGE_B)

__global__ __launch_bounds__(256, 2) void hgemm3_nt(const __nv_bfloat16* __restrict__ A,
                                                    const __nv_bfloat16* __restrict__ Bw)
{
    extern __shared__ __align__(16) __nv_bfloat16 sm3[];
    const uint32_t sbase = smem_u32(sm3);

    const int tid  = threadIdx.x;
    const int lane = tid & 31;
    const int warp = tid >> 5;
    const int wm   = warp & 1;
    const int wn   = warp >> 1;
    const int bm   = blockIdx.y * 128;
    const int bn   = blockIdx.x * 128;

    const int r0 = tid >> 2, o = tid & 3;
    const uint32_t e0b = (uint32_t)(r0 * RS + o * 8) * 2;
    const uint32_t e1b = (uint32_t)((r0 + 64) * RS + o * 8) * 2;

    const __nv_bfloat16* Ag = A  + (size_t)bm * K2;
    const __nv_bfloat16* Bg = Bw + (size_t)bn * K2;
    const __nv_bfloat16* a0p = Ag + (size_t)r0 * K2 + o * 8;
    const __nv_bfloat16* a1p = Ag + (size_t)(r0 + 64) * K2 + o * 8;
    const __nv_bfloat16* b0p = Bg + (size_t)r0 * K2 + o * 8;
    const __nv_bfloat16* b1p = Bg + (size_t)(r0 + 64) * K2 + o * 8;

#define ISSUE3(buf, ch) do {                                                   \
    const int ko = (ch) * 32;                                                  \
    const uint32_t base = sbase + (buf) * STAGE_B;                             \
    CPA16(base + e0b,              a0p + ko);                                  \
    CPA16(base + e1b,              a1p + ko);                                  \
    CPA16(base + TILE_B + e0b,     a0p + ko + 1024);                           \
    CPA16(base + TILE_B + e1b,     a1p + ko + 1024);                           \
    CPA16(base + 2*TILE_B + e0b,   b0p + ko);                                  \
    CPA16(base + 2*TILE_B + e1b,   b1p + ko);                                  \
    CPA16(base + 3*TILE_B + e0b,   b0p + ko + 1024);                           \
    CPA16(base + 3*TILE_B + e1b,   b1p + ko + 1024);                           \
    asm volatile("cp.async.commit_group;");                                    \
} while (0)

    ISSUE3(0, 0);
    ISSUE3(1, 1);

    float acc[4][4][4];
#pragma unroll
    for (int mi = 0; mi < 4; mi++)
#pragma unroll
        for (int ni = 0; ni < 4; ni++)
#pragma unroll
            for (int r = 0; r < 4; r++) acc[mi][ni][r] = 0.f;

    const int arow  = wm * 64 + (lane & 15);
    const int acol8 = (lane >> 4) * 8;
    const int brow  = (lane & 7) + ((lane & 16) ? 8 : 0);
    const int bcol8 = (lane & 8) ? 8 : 0;

    for (int c = 0; c < NCHUNK; c++) {
        const int buf = c & 1;
        if (c + 1 < NCHUNK) asm volatile("cp.async.wait_group 1;");
        else                asm volatile("cp.async.wait_group 0;");
        __syncthreads();

        const __nv_bfloat16* sAh = sm3 + buf * STAGE_E;
        const __nv_bfloat16* sAl = sAh + TILE_E;
        const __nv_bfloat16* sBh = sAh + 2 * TILE_E;
        const __nv_bfloat16* sBl = sAh + 3 * TILE_E;

#pragma unroll
        for (int kk = 0; kk < 2; kk++) {
            uint32_t ah[4][4], al[4][4], bh[2][4];
#pragma unroll
            for (int mi = 0; mi < 4; mi++) {
                uint32_t addr = smem_u32(&sAh[(arow + mi * 16) * RS + kk * 16 + acol8]);
                LDSM4(ah[mi][0], ah[mi][1], ah[mi][2], ah[mi][3], addr);
            }
#pragma unroll
            for (int mi = 0; mi < 4; mi++) {
                uint32_t addr = smem_u32(&sAl[(arow + mi * 16) * RS + kk * 16 + acol8]);
                LDSM4(al[mi][0], al[mi][1], al[mi][2], al[mi][3], addr);
            }
#pragma unroll
            for (int np = 0; np < 2; np++) {
                uint32_t addr = smem_u32(&sBh[(wn * 32 + np * 16 + brow) * RS
                                              + kk * 16 + bcol8]);
                LDSM4(bh[np][0], bh[np][1], bh[np][2], bh[np][3], addr);
            }
#pragma unroll
            for (int mi = 0; mi < 4; mi++)
#pragma unroll
                for (int np = 0; np < 2; np++) {
                    MMA16816(acc[mi][2*np],   ah[mi][0], ah[mi][1], ah[mi][2], ah[mi][3],
                             bh[np][0], bh[np][1]);
                    MMA16816(acc[mi][2*np+1], ah[mi][0], ah[mi][1], ah[mi][2], ah[mi][3],
                             bh[np][2], bh[np][3]);
                }
#pragma unroll
            for (int mi = 0; mi < 4; mi++)
#pragma unroll
                for (int np = 0; np < 2; np++) {
                    MMA16816(acc[mi][2*np],   al[mi][0], al[mi][1], al[mi][2], al[mi][3],
                             bh[np][0], bh[np][1]);
                    MMA16816(acc[mi][2*np+1], al[mi][0], al[mi][1], al[mi][2], al[mi][3],
                             bh[np][2], bh[np][3]);
                }
#pragma unroll
            for (int np = 0; np < 2; np++) {
                uint32_t bl[4];
                uint32_t addr = smem_u32(&sBl[(wn * 32 + np * 16 + brow) * RS
                                              + kk * 16 + bcol8]);
                LDSM4(bl[0], bl[1], bl[2], bl[3], addr);
#pragma unroll
                for (int mi = 0; mi < 4; mi++) {
                    MMA16816(acc[mi][2*np],   ah[mi][0], ah[mi][1], ah[mi][2], ah[mi][3],
                             bl[0], bl[1]);
                    MMA16816(acc[mi][2*np+1], ah[mi][0], ah[mi][1], ah[mi][2], ah[mi][3],
                             bl[2], bl[3]);
                }
            }
        }

        __syncthreads();
        if (c + 2 < NCHUNK) ISSUE3(buf, c + 2);
    }

    // QKV epilogue: bf16 hi/lo split; q,k row-major per head; v transposed
    const int gid = lane >> 2;
    const int tig = lane & 3;
#pragma unroll
    for (int mi = 0; mi < 4; mi++) {
        const int m0 = bm + wm * 64 + mi * 16 + gid;
#pragma unroll
        for (int ni = 0; ni < 4; ni++) {
            const int n0 = bn + wn * 32 + ni * 8 + tig * 2;
            const int which = n0 >> 10;
            const int rem = n0 & 1023;
            const int h = rem >> 6;
            const int d = rem & 63;
#pragma unroll
            for (int half = 0; half < 2; half++) {
                const int m = m0 + half * 8;
                const int b = m >> 11;
                const int t = m & 2047;
                const size_t bh_ = (size_t)(b * HH + h);
                float v0 = acc[mi][ni][2 * half];
                float v1 = acc[mi][ni][2 * half + 1];
                uint32_t hi2 = pack_bf16(v0, v1);
                float lo0 = v0 - bf16lo_f(hi2);
                float lo1 = v1 - bf16hi_f(hi2);
                uint32_t lo2 = pack_bf16(lo0, lo1);
                if (which == 2) {
                    const size_t base = bh_ * DKK * TT + (size_t)t;
                    g_vth[base + (size_t)d * TT]       = __float2bfloat16(v0);
                    g_vth[base + (size_t)(d + 1) * TT] = __float2bfloat16(v1);
                    g_vtl[base + (size_t)d * TT]       = __float2bfloat16(lo0);
                    g_vtl[base + (size_t)(d + 1) * TT] = __float2bfloat16(lo1);
                } else {
                    const size_t off = bh_ * TT * DKK + (size_t)t * DKK + d;
                    __nv_bfloat16* ph = (which == 0) ? g_qh : g_kh;
                    __nv_bfloat16* pl = (which == 0) ? g_ql : g_kl;
                    *(uint32_t*)(ph + off) = hi2;
                    *(uint32_t*)(pl + off) = lo2;
                }
            }
        }
    }
}

// ---------------------------------------------------------------------------
// fp16 2-term GEMM NT (proj): C = A'[4096,2048] * B'[1024,2048]^T, fp32 out.
// A' = [Oh|Ol] fp16, B' = [Wh|Wh] fp16 -> C = O * Wh^T exactly.
// Structure = verified R7 hgemm_nt with K=2048, f16 MMA.
// ---------------------------------------------------------------------------
#define NCHF (K2 / 32)    // 64

__global__ __launch_bounds__(256) void hgemm2_f16(const __half* __restrict__ A,
                                                  const __half* __restrict__ Bw,
                                                  float* __restrict__ Cout)
{
    __shared__ __align__(16) __half sA[2][128 * RS];
    __shared__ __align__(16) __half sB[2][128 * RS];

    const int tid  = threadIdx.x;
    const int lane = tid & 31;
    const int warp = tid >> 5;
    const int wm   = warp & 1;
    const int wn   = warp >> 1;
    const int bm   = blockIdx.y * 128;
    const int bn   = blockIdx.x * 128;

    const int r0 = tid >> 2, o0 = tid & 3;
    const int r1 = (tid + 256) >> 2, o1 = (tid + 256) & 3;

    const __half* Ag = A  + (size_t)bm * K2;
    const __half* Bg = Bw + (size_t)bn * K2;

    uint32_t sa0[2], sa1[2], sb0[2], sb1[2];
#pragma unroll
    for (int s = 0; s < 2; s++) {
        sa0[s] = smem_u32(&sA[s][r0 * RS + o0 * 8]);
        sa1[s] = smem_u32(&sA[s][r1 * RS + o1 * 8]);
        sb0[s] = smem_u32(&sB[s][r0 * RS + o0 * 8]);
        sb1[s] = smem_u32(&sB[s][r1 * RS + o1 * 8]);
    }

#define ISSUE_F(buf, ch) do {                                                  \
    const __half* ap0 = Ag + (size_t)r0 * K2 + (ch) * 32 + o0 * 8;             \
    const __half* ap1 = Ag + (size_t)r1 * K2 + (ch) * 32 + o1 * 8;             \
    const __half* bp0 = Bg + (size_t)r0 * K2 + (ch) * 32 + o0 * 8;             \
    const __half* bp1 = Bg + (size_t)r1 * K2 + (ch) * 32 + o1 * 8;             \
    CPA16(sa0[buf], ap0); CPA16(sa1[buf], ap1);                                \
    CPA16(sb0[buf], bp0); CPA16(sb1[buf], bp1);                                \
    asm volatile("cp.async.commit_group;");                                    \
} while (0)

    ISSUE_F(0, 0);
    ISSUE_F(1, 1);

    float acc[4][4][4];
#pragma unroll
    for (int mi = 0; mi < 4; mi++)
#pragma unroll
        for (int ni = 0; ni < 4; ni++)
#pragma unroll
            for (int r = 0; r < 4; r++) acc[mi][ni][r] = 0.f;

    const int l16 = lane & 15;

    for (int c = 0; c < NCHF; c++) {
        const int buf = c & 1;
        if (c + 1 < NCHF) asm volatile("cp.async.wait_group 1;");
        else              asm volatile("cp.async.wait_group 0;");
        __syncthreads();

        const __half* sAb = sA[buf];
        const __half* sBb = sB[buf];

#pragma unroll
        for (int kk = 0; kk < 2; kk++) {
            uint32_t af[4][4];
            uint32_t bf[4][2];
#pragma unroll
            for (int mi = 0; mi < 4; mi++) {
                uint32_t addr = smem_u32(&sAb[(wm * 64 + mi * 16 + (lane & 15)) * RS
                                              + kk * 16 + (lane >> 4) * 8]);
                LDSM4(af[mi][0], af[mi][1], af[mi][2], af[mi][3], addr);
            }
#pragma unroll
            for (int ni = 0; ni < 4; ni++) {
                uint32_t addr = smem_u32(&sBb[(wn * 32 + ni * 8 + (l16 & 7)) * RS
                                              + kk * 16 + (l16 >> 3) * 8]);
                LDSM2(bf[ni][0], bf[ni][1], addr);
            }
#pragma unroll
            for (int mi = 0; mi < 4; mi++)
#pragma unroll
                for (int ni = 0; ni < 4; ni++)
                    MMA16816H(acc[mi][ni], af[mi][0], af[mi][1], af[mi][2], af[mi][3],
                              bf[ni][0], bf[ni][1]);
        }

        __syncthreads();
        if (c + 2 < NCHF) ISSUE_F(buf, c + 2);
    }

    const int gid = lane >> 2;
    const int tig = lane & 3;
#pragma unroll
    for (int mi = 0; mi < 4; mi++) {
        const int m0 = bm + wm * 64 + mi * 16 + gid;
#pragma unroll
        for (int ni = 0; ni < 4; ni++) {
            const int n0 = bn + wn * 32 + ni * 8 + tig * 2;
            *(float2*)(Cout + (size_t)m0 * 1024 + n0) =
                make_float2(acc[mi][ni][0], acc[mi][ni][1]);
            *(float2*)(Cout + (size_t)(m0 + 8) * 1024 + n0) =
                make_float2(acc[mi][ni][2], acc[mi][ni][3]);
        }
    }
}

// ---------------------------------------------------------------------------
// Tensor-core flash attention, causal (verified R10); epilogue -> fp16 [Oh|Ol]
// ---------------------------------------------------------------------------
#define QTILE 128
#define KTILE 64
#define ARS 72
#define QELEMS (QTILE * ARS)
#define KTELEMS (KTILE * ARS)
#define STG0 (2 * QELEMS)
#define STG_STRIDE (4 * KTELEMS)
#define ATT_SMEM_B ((STG0 + 2 * STG_STRIDE) * 2)

__global__ __launch_bounds__(256) void attn_mma()
{
    extern __shared__ __align__(16) __nv_bfloat16 sm[];

    const int tid  = threadIdx.x;
    const int lane = tid & 31;
    const int w    = tid >> 5;
    const int qt   = gridDim.x - 1 - blockIdx.x;
    const int h    = blockIdx.y;
    const int b    = blockIdx.z;
    const int q0   = qt * QTILE;
    const size_t bh = (size_t)(b * HH + h);
    const int njt  = 2 * qt + 2;

    const __nv_bfloat16* Qh = g_qh + bh * TT * DKK;
    const __nv_bfloat16* Ql = g_ql + bh * TT * DKK;
    const __nv_bfloat16* Kh = g_kh + bh * TT * DKK;
    const __nv_bfloat16* Kl = g_kl + bh * TT * DKK;
    const __nv_bfloat16* Vh = g_vth + bh * DKK * TT;
    const __nv_bfloat16* Vl = g_vtl + bh * DKK * TT;

#pragma unroll
    for (int i = 0; i < 8; i++) {
        int lin = tid + i * 256;
        int arr = lin >> 10;
        int r   = (lin & 1023) >> 3;
        int ch  = lin & 7;
        const __nv_bfloat16* src = (arr ? Ql : Qh) + (size_t)(q0 + r) * DKK + ch * 8;
        uint32_t dst = smem_u32(&sm[arr * QELEMS + r * ARS + ch * 8]);
        CPA16(dst, src);
    }

    const int lr = tid >> 3, lch = tid & 7;
#define ISSUE_KV(jt, s) do {                                                      \
    int k0_ = (jt) * KTILE;                                                       \
    __nv_bfloat16* base = sm + STG0 + (s) * STG_STRIDE;                           \
    CPA16(smem_u32(&base[lr * ARS + lch * 8]),                                    \
          Kh + (size_t)(k0_ + lr) * DKK + lch * 8);                               \
    CPA16(smem_u32(&base[(lr + 32) * ARS + lch * 8]),                             \
          Kh + (size_t)(k0_ + lr + 32) * DKK + lch * 8);                          \
    CPA16(smem_u32(&base[KTELEMS + lr * ARS + lch * 8]),                          \
          Kl + (size_t)(k0_ + lr) * DKK + lch * 8);                               \
    CPA16(smem_u32(&base[KTELEMS + (lr + 32) * ARS + lch * 8]),                   \
          Kl + (size_t)(k0_ + lr + 32) * DKK + lch * 8);                          \
    CPA16(smem_u32(&base[2 * KTELEMS + lr * ARS + lch * 8]),                      \
          Vh + (size_t)lr * TT + k0_ + lch * 8);                                  \
    CPA16(smem_u32(&base[2 * KTELEMS + (lr + 32) * ARS + lch * 8]),               \
          Vh + (size_t)(lr + 32) * TT + k0_ + lch * 8);                           \
    CPA16(smem_u32(&base[3 * KTELEMS + lr * ARS + lch * 8]),                      \
          Vl + (size_t)lr * TT + k0_ + lch * 8);                                  \
    CPA16(smem_u32(&base[3 * KTELEMS + (lr + 32) * ARS + lch * 8]),               \
          Vl + (size_t)(lr + 32) * TT + k0_ + lch * 8);                           \
    asm volatile("cp.async.commit_group;");                                       \
} while (0)

    ISSUE_KV(0, 0);
    ISSUE_KV(1, 1);

    float oacc[8][4];
#pragma unroll
    for (int ni = 0; ni < 8; ni++)
#pragma unroll
        for (int r = 0; r < 4; r++) oacc[ni][r] = 0.f;
    float mrow[2] = {-1e30f, -1e30f};
    float lrow[2] = {0.f, 0.f};

    uint32_t ah[4][4];
    bool ah_loaded = false;

    const int arow = w * 16 + (lane & 15);
    const int acol8 = (lane >> 4) * 8;
    const int brow = (lane & 7) + ((lane & 16) ? 8 : 0);
    const int bcol8 = (lane & 8) ? 8 : 0;
    const int rr = lane >> 2;
    const int cc2 = (lane & 3) * 2;

    for (int jt = 0; jt < njt; jt++) {
        const int s = jt & 1;
        if (jt + 1 < njt) asm volatile("cp.async.wait_group 1;");
        else              asm volatile("cp.async.wait_group 0;");
        __syncthreads();

        __nv_bfloat16* sKh = sm + STG0 + s * STG_STRIDE;
        __nv_bfloat16* sKl = sKh + KTELEMS;
        __nv_bfloat16* sVh = sKh + 2 * KTELEMS;
        __nv_bfloat16* sVl = sKh + 3 * KTELEMS;

        if (!ah_loaded) {
            ah_loaded = true;
#pragma unroll
            for (int kk = 0; kk < 4; kk++) {
                uint32_t addr = smem_u32(&sm[arow * ARS + kk * 16 + acol8]);
                LDSM4(ah[kk][0], ah[kk][1], ah[kk][2], ah[kk][3], addr);
            }
        }

        float sacc[8][4];
#pragma unroll
        for (int ni = 0; ni < 8; ni++)
#pragma unroll
            for (int r = 0; r < 4; r++) sacc[ni][r] = 0.f;

#pragma unroll
        for (int kk = 0; kk < 4; kk++) {
            uint32_t al4[4];
            {
                uint32_t addr = smem_u32(&sm[QELEMS + arow * ARS + kk * 16 + acol8]);
                LDSM4(al4[0], al4[1], al4[2], al4[3], addr);
            }
            uint32_t bh4[4][4];
#pragma unroll
            for (int np = 0; np < 4; np++) {
                uint32_t addr = smem_u32(&sKh[(np * 16 + brow) * ARS + kk * 16 + bcol8]);
                LDSM4(bh4[np][0], bh4[np][1], bh4[np][2], bh4[np][3], addr);
            }
#pragma unroll
            for (int np = 0; np < 4; np++) {
                MMA16816(sacc[2*np],   ah[kk][0], ah[kk][1], ah[kk][2], ah[kk][3],
                         bh4[np][0], bh4[np][1]);
                MMA16816(sacc[2*np+1], ah[kk][0], ah[kk][1], ah[kk][2], ah[kk][3],
                         bh4[np][2], bh4[np][3]);
            }
#pragma unroll
            for (int np = 0; np < 4; np++) {
                MMA16816(sacc[2*np],   al4[0], al4[1], al4[2], al4[3],
                         bh4[np][0], bh4[np][1]);
                MMA16816(sacc[2*np+1], al4[0], al4[1], al4[2], al4[3],
                         bh4[np][2], bh4[np][3]);
            }
#pragma unroll
            for (int np = 0; np < 4; np++) {
                uint32_t bl4[4];
                uint32_t addr = smem_u32(&sKl[(np * 16 + brow) * ARS + kk * 16 + bcol8]);
                LDSM4(bl4[0], bl4[1], bl4[2], bl4[3], addr);
                MMA16816(sacc[2*np],   ah[kk][0], ah[kk][1], ah[kk][2], ah[kk][3],
                         bl4[0], bl4[1]);
                MMA16816(sacc[2*np+1], ah[kk][0], ah[kk][1], ah[kk][2], ah[kk][3],
                         bl4[2], bl4[3]);
            }
        }

        const int k0 = jt * KTILE;
        const int r0 = q0 + w * 16 + rr;
        const int r1 = r0 + 8;
        const bool need_mask = (k0 + KTILE - 1 > r0);
#pragma unroll
        for (int ni = 0; ni < 8; ni++) {
            const int col = k0 + ni * 8 + cc2;
#pragma unroll
            for (int c = 0; c < 2; c++) {
                sacc[ni][c]     *= 0.125f;
                sacc[ni][2 + c] *= 0.125f;
                if (need_mask) {
                    if (col + c > r0) sacc[ni][c]     = -1e30f;
                    if (col + c > r1) sacc[ni][2 + c] = -1e30f;
                }
            }
        }

        float mx0 = -1e30f, mx1 = -1e30f;
#pragma unroll
        for (int ni = 0; ni < 8; ni++) {
            mx0 = fmaxf(mx0, fmaxf(sacc[ni][0], sacc[ni][1]));
            mx1 = fmaxf(mx1, fmaxf(sacc[ni][2], sacc[ni][3]));
        }
        mx0 = fmaxf(mx0, __shfl_xor_sync(0xffffffffu, mx0, 1));
        mx0 = fmaxf(mx0, __shfl_xor_sync(0xffffffffu, mx0, 2));
        mx1 = fmaxf(mx1, __shfl_xor_sync(0xffffffffu, mx1, 1));
        mx1 = fmaxf(mx1, __shfl_xor_sync(0xffffffffu, mx1, 2));
        const float mn0 = fmaxf(mrow[0], mx0);
        const float mn1 = fmaxf(mrow[1], mx1);
        const float al0 = __expf(mrow[0] - mn0);
        const float al1 = __expf(mrow[1] - mn1);
        mrow[0] = mn0; mrow[1] = mn1;
        float sum0 = 0.f, sum1 = 0.f;
#pragma unroll
        for (int ni = 0; ni < 8; ni++) {
            sacc[ni][0] = __expf(sacc[ni][0] - mn0); sum0 += sacc[ni][0];
            sacc[ni][1] = __expf(sacc[ni][1] - mn0); sum0 += sacc[ni][1];
            sacc[ni][2] = __expf(sacc[ni][2] - mn1); sum1 += sacc[ni][2];
            sacc[ni][3] = __expf(sacc[ni][3] - mn1); sum1 += sacc[ni][3];
        }
        sum0 += __shfl_xor_sync(0xffffffffu, sum0, 1);
        sum0 += __shfl_xor_sync(0xffffffffu, sum0, 2);
        sum1 += __shfl_xor_sync(0xffffffffu, sum1, 1);
        sum1 += __shfl_xor_sync(0xffffffffu, sum1, 2);
        lrow[0] = lrow[0] * al0 + sum0;
        lrow[1] = lrow[1] * al1 + sum1;
#pragma unroll
        for (int ni = 0; ni < 8; ni++) {
            oacc[ni][0] *= al0; oacc[ni][1] *= al0;
            oacc[ni][2] *= al1; oacc[ni][3] *= al1;
        }

#pragma unroll
        for (int kk = 0; kk < 4; kk++) {
            const int b2 = 2 * kk, b3 = 2 * kk + 1;
            uint32_t pah[4], pal[4];
            pah[0] = pack_bf16(sacc[b2][0], sacc[b2][1]);
            pah[1] = pack_bf16(sacc[b2][2], sacc[b2][3]);
            pah[2] = pack_bf16(sacc[b3][0], sacc[b3][1]);
            pah[3] = pack_bf16(sacc[b3][2], sacc[b3][3]);
            pal[0] = pack_bf16(sacc[b2][0] - bf16lo_f(pah[0]), sacc[b2][1] - bf16hi_f(pah[0]));
            pal[1] = pack_bf16(sacc[b2][2] - bf16lo_f(pah[1]), sacc[b2][3] - bf16hi_f(pah[1]));
            pal[2] = pack_bf16(sacc[b3][0] - bf16lo_f(pah[2]), sacc[b3][1] - bf16hi_f(pah[2]));
            pal[3] = pack_bf16(sacc[b3][2] - bf16lo_f(pah[3]), sacc[b3][3] - bf16hi_f(pah[3]));
            uint32_t vh4[4][4];
#pragma unroll
            for (int dp = 0; dp < 4; dp++) {
                uint32_t addr = smem_u32(&sVh[(dp * 16 + brow) * ARS + kk * 16 + bcol8]);
                LDSM4(vh4[dp][0], vh4[dp][1], vh4[dp][2], vh4[dp][3], addr);
            }
#pragma unroll
            for (int dp = 0; dp < 4; dp++) {
                MMA16816(oacc[2*dp],   pah[0], pah[1], pah[2], pah[3],
                         vh4[dp][0], vh4[dp][1]);
                MMA16816(oacc[2*dp+1], pah[0], pah[1], pah[2], pah[3],
                         vh4[dp][2], vh4[dp][3]);
            }
#pragma unroll
            for (int dp = 0; dp < 4; dp++) {
                MMA16816(oacc[2*dp],   pal[0], pal[1], pal[2], pal[3],
                         vh4[dp][0], vh4[dp][1]);
                MMA16816(oacc[2*dp+1], pal[0], pal[1], pal[2], pal[3],
                         vh4[dp][2], vh4[dp][3]);
            }
#pragma unroll
            for (int dp = 0; dp < 4; dp++) {
                uint32_t vl4[4];
                uint32_t addr = smem_u32(&sVl[(dp * 16 + brow) * ARS + kk * 16 + bcol8]);
                LDSM4(vl4[0], vl4[1], vl4[2], vl4[3], addr);
                MMA16816(oacc[2*dp],   pah[0], pah[1], pah[2], pah[3], vl4[0], vl4[1]);
                MMA16816(oacc[2*dp+1], pah[0], pah[1], pah[2], pah[3], vl4[2], vl4[3]);
            }
        }

        __syncthreads();
        if (jt + 2 < njt) ISSUE_KV(jt + 2, s);
    }

    // epilogue: normalize, fp16 hi/lo split, write g_att16 [Oh | Ol]
    const float inv0 = 1.f / lrow[0];
    const float inv1 = 1.f / lrow[1];
    const int row0 = q0 + w * 16 + rr;
    const size_t m0 = (size_t)b * TT + row0;
    __half* dst0 = g_att16 + m0 * K2 + h * 64;
    __half* dst1 = g_att16 + (m0 + 8) * K2 + h * 64;
#pragma unroll
    for (int ni = 0; ni < 8; ni++) {
        const int d = ni * 8 + cc2;
        float v0 = oacc[ni][0] * inv0, v1 = oacc[ni][1] * inv0;
        float v2 = oacc[ni][2] * inv1, v3 = oacc[ni][3] * inv1;
        __half h0 = __float2half_rn(v0), h1 = __float2half_rn(v1);
        __half h2 = __float2half_rn(v2), h3 = __float2half_rn(v3);
        float l0 = v0 - __half2float(h0), l1 = v1 - __half2float(h1);
        float l2 = v2 - __half2float(h2), l3 = v3 - __half2float(h3);
        *(uint32_t*)(dst0 + d)        = pack_f16(__half2float(h0), __half2float(h1));
        *(uint32_t*)(dst0 + 1024 + d) = pack_f16(l0, l1);
        *(uint32_t*)(dst1 + d)        = pack_f16(__half2float(h2), __half2float(h3));
        *(uint32_t*)(dst1 + 1024 + d) = pack_f16(l2, l3);
    }
}

// ---------------------------------------------------------------------------
extern "C" void kernel_launch(void* const* d_in, const int* in_sizes, int n_in,
                              void* d_out, int out_size)
{
    const float* x      = (const float*)d_in[0];   // [2, 2048, 1024]
    const float* w_attn = (const float*)d_in[1];   // [3072, 1024]
    const float* w_proj = (const float*)d_in[2];   // [1024, 1024]
    float* out = (float*)d_out;                    // [2, 2048, 1024]

    cudaFuncSetAttribute(hgemm3_nt,
                         cudaFuncAttributeMaxDynamicSharedMemorySize, GSMEM_B);
    cudaFuncSetAttribute(attn_mma,
                         cudaFuncAttributeMaxDynamicSharedMemorySize, ATT_SMEM_B);

    void *xs, *was, *att16, *wp16;
    cudaGetSymbolAddress(&xs,    g_xs);
    cudaGetSymbolAddress(&was,   g_was);
    cudaGetSymbolAddress(&att16, g_att16);
    cudaGetSymbolAddress(&wp16,  g_wp16);

    // 0) splits: bf16 [hi|lo] for x, w_attn; fp16 [Wh|Wh] for w_proj
    split_kernel<<<(BB*TT*CC/4 + 255)/256, 256>>>(x,      (__nv_bfloat16*)xs,  BB*TT*CC);
    split_kernel<<<(3*CC*CC/4  + 255)/256, 256>>>(w_attn, (__nv_bfloat16*)was, 3*CC*CC);
    split_w16<<<(CC*CC/4 + 255)/256, 256>>>(w_proj, (__half*)wp16, CC*CC);

    // 1) QKV projection (3-term bf16 GEMM) -> bf16 hi/lo per-head (V transposed)
    {
        dim3 grid(3 * CC / 128, (BB * TT) / 128);  // (24, 32)
        hgemm3_nt<<<grid, 256, GSMEM_B>>>((const __nv_bfloat16*)xs,
                                          (const __nv_bfloat16*)was);
    }

    // 2) causal flash attention on tensor cores -> g_att16 [Oh|Ol] fp16
    {
        dim3 grid(TT / QTILE, HH, BB);             // (16, 16, 2)
        attn_mma<<<grid, 256, ATT_SMEM_B>>>();
    }

    // 3) output projection: fp16 2-term GEMM (O * Wh^T)
    {
        dim3 grid(CC / 128, (BB * TT) / 128);      // (8, 32)
        hgemm2_f16<<<grid, 256>>>((const __half*)att16, (const __half*)wp16, out);
    }
}

// round 12
// speedup vs baseline: 2.9665x; 1.1384x over previous
#include <cuda_runtime.h>
#include <cuda_bf16.h>
#include <cuda_fp16.h>
#include <math.h>
#include <cstdint>

#define BB 2
#define TT 2048
#define CC 1024
#define HH 16
#define DKK 64
#define K2 2048   // [hi | lo] compact layout

// bf16 scratch (QKV GEMM operands)
__device__ __nv_bfloat16 g_xs[(size_t)BB*TT*K2];       // x'      [4096, 2048]
__device__ __nv_bfloat16 g_was[(size_t)3*CC*K2];       // w_attn' [3072, 2048]
// fp16 scratch (attention + proj path)
__device__ __half g_q16h[(size_t)BB*HH*TT*DKK];
__device__ __half g_q16l[(size_t)BB*HH*TT*DKK];
__device__ __half g_k16[(size_t)BB*HH*TT*DKK];
__device__ __half g_vt16[(size_t)BB*HH*DKK*TT];        // V^T [b,h,d,t]
__device__ __half g_att16[(size_t)BB*TT*K2];           // O  [4096, 2048] = [Oh|Ol]
__device__ __half g_wp16[(size_t)CC*K2];               // W' [1024, 2048] = [Wh|Wh]

__device__ __forceinline__ uint32_t smem_u32(const void* p) {
    uint32_t a;
    asm("{ .reg .u64 t; cvta.to.shared.u64 t, %1; cvt.u32.u64 %0, t; }" : "=r"(a) : "l"(p));
    return a;
}

__device__ __forceinline__ uint32_t pack_bf16(float a, float b) {
    uint32_t r;
    asm("cvt.rn.bf16x2.f32 %0, %1, %2;" : "=r"(r) : "f"(b), "f"(a));
    return r;
}
__device__ __forceinline__ float bf16lo_f(uint32_t r) { return __uint_as_float(r << 16); }
__device__ __forceinline__ float bf16hi_f(uint32_t r) { return __uint_as_float(r & 0xFFFF0000u); }

__device__ __forceinline__ uint32_t pack_f16(float a, float b) {
    __half2 h = __floats2half2_rn(a, b);   // a -> low, b -> high
    return *(uint32_t*)&h;
}
__device__ __forceinline__ float f16lo_f(uint32_t r) {
    return __half2float(__ushort_as_half((unsigned short)(r & 0xFFFFu)));
}
__device__ __forceinline__ float f16hi_f(uint32_t r) {
    return __half2float(__ushort_as_half((unsigned short)(r >> 16)));
}

#define MMA16816(d, a0,a1,a2,a3, b0,b1) \
    asm volatile("mma.sync.aligned.m16n8k16.row.col.f32.bf16.bf16.f32 " \
        "{%0,%1,%2,%3}, {%4,%5,%6,%7}, {%8,%9}, {%0,%1,%2,%3};" \
        : "+f"((d)[0]), "+f"((d)[1]), "+f"((d)[2]), "+f"((d)[3]) \
        : "r"(a0), "r"(a1), "r"(a2), "r"(a3), "r"(b0), "r"(b1))

#define MMA16816H(d, a0,a1,a2,a3, b0,b1) \
    asm volatile("mma.sync.aligned.m16n8k16.row.col.f32.f16.f16.f32 " \
        "{%0,%1,%2,%3}, {%4,%5,%6,%7}, {%8,%9}, {%0,%1,%2,%3};" \
        : "+f"((d)[0]), "+f"((d)[1]), "+f"((d)[2]), "+f"((d)[3]) \
        : "r"(a0), "r"(a1), "r"(a2), "r"(a3), "r"(b0), "r"(b1))

#define LDSM4(r0,r1,r2,r3, addr) \
    asm volatile("ldmatrix.sync.aligned.m8n8.x4.shared.b16 {%0,%1,%2,%3}, [%4];" \
        : "=r"(r0), "=r"(r1), "=r"(r2), "=r"(r3) : "r"(addr))

#define LDSM2(r0,r1, addr) \
    asm volatile("ldmatrix.sync.aligned.m8n8.x2.shared.b16 {%0,%1}, [%2];" \
        : "=r"(r0), "=r"(r1) : "r"(addr))

#define CPA16(dst, src) \
    asm volatile("cp.async.cg.shared.global [%0], [%1], 16;" :: "r"(dst), "l"(src))

// ---------------------------------------------------------------------------
// split: fp32 [R,1024] -> bf16 [R,2048] = [hi | lo]   (QKV operands)
// ---------------------------------------------------------------------------
__global__ __launch_bounds__(256) void split_kernel(const float* __restrict__ in,
                                                    __nv_bfloat16* __restrict__ out,
                                                    int n)
{
    int i4 = (blockIdx.x * 256 + threadIdx.x) * 4;
    if (i4 >= n) return;
    float4 v = *(const float4*)(in + i4);
    int r = i4 >> 10;
    int c = i4 & 1023;
    __nv_bfloat16 h0 = __float2bfloat16(v.x);
    __nv_bfloat16 h1 = __float2bfloat16(v.y);
    __nv_bfloat16 h2 = __float2bfloat16(v.z);
    __nv_bfloat16 h3 = __float2bfloat16(v.w);
    __nv_bfloat16 l0 = __float2bfloat16(v.x - __bfloat162float(h0));
    __nv_bfloat16 l1 = __float2bfloat16(v.y - __bfloat162float(h1));
    __nv_bfloat16 l2 = __float2bfloat16(v.z - __bfloat162float(h2));
    __nv_bfloat16 l3 = __float2bfloat16(v.w - __bfloat162float(h3));
    __nv_bfloat162* ph = (__nv_bfloat162*)(out + (size_t)r * K2 + c);
    __nv_bfloat162* pl = (__nv_bfloat162*)(out + (size_t)r * K2 + 1024 + c);
    ph[0] = __nv_bfloat162(h0, h1); ph[1] = __nv_bfloat162(h2, h3);
    pl[0] = __nv_bfloat162(l0, l1); pl[1] = __nv_bfloat162(l2, l3);
}

// ---------------------------------------------------------------------------
// split_w16: fp32 W [1024,1024] -> fp16 [1024,2048] = [Wh | Wh] (duplicated)
// ---------------------------------------------------------------------------
__global__ __launch_bounds__(256) void split_w16(const float* __restrict__ in,
                                                 __half* __restrict__ out, int n)
{
    int i4 = (blockIdx.x * 256 + threadIdx.x) * 4;
    if (i4 >= n) return;
    float4 v = *(const float4*)(in + i4);
    int r = i4 >> 10;
    int c = i4 & 1023;
    uint32_t p0 = pack_f16(v.x, v.y);
    uint32_t p1 = pack_f16(v.z, v.w);
    uint32_t* d0 = (uint32_t*)(out + (size_t)r * K2 + c);
    uint32_t* d1 = (uint32_t*)(out + (size_t)r * K2 + 1024 + c);
    d0[0] = p0; d0[1] = p1;
    d1[0] = p0; d1[1] = p1;
}

// ---------------------------------------------------------------------------
// 3-term bf16 GEMM NT (QKV): C = Ah*Bh^T + Al*Bh^T + Ah*Bl^T, base K=1024.
// Epilogue -> fp16: Q hi/lo pair, K single, V^T single.
// ---------------------------------------------------------------------------
#define RS 40
#define NCHUNK 32
#define TILE_E (128 * RS)
#define TILE_B (TILE_E * 2)
#define STAGE_E (4 * TILE_E)
#define STAGE_B (4 * TILE_B)
#define GSMEM_B (2 * STAGE_B)

__global__ __launch_bounds__(256, 2) void hgemm3_nt(const __nv_bfloat16* __restrict__ A,
                                                    const __nv_bfloat16* __restrict__ Bw)
{
    extern __shared__ __align__(16) __nv_bfloat16 sm3[];
    const uint32_t sbase = smem_u32(sm3);

    const int tid  = threadIdx.x;
    const int lane = tid & 31;
    const int warp = tid >> 5;
    const int wm   = warp & 1;
    const int wn   = warp >> 1;
    const int bm   = blockIdx.y * 128;
    const int bn   = blockIdx.x * 128;

    const int r0 = tid >> 2, o = tid & 3;
    const uint32_t e0b = (uint32_t)(r0 * RS + o * 8) * 2;
    const uint32_t e1b = (uint32_t)((r0 + 64) * RS + o * 8) * 2;

    const __nv_bfloat16* Ag = A  + (size_t)bm * K2;
    const __nv_bfloat16* Bg = Bw + (size_t)bn * K2;
    const __nv_bfloat16* a0p = Ag + (size_t)r0 * K2 + o * 8;
    const __nv_bfloat16* a1p = Ag + (size_t)(r0 + 64) * K2 + o * 8;
    const __nv_bfloat16* b0p = Bg + (size_t)r0 * K2 + o * 8;
    const __nv_bfloat16* b1p = Bg + (size_t)(r0 + 64) * K2 + o * 8;

#define ISSUE3(buf, ch) do {                                                   \
    const int ko = (ch) * 32;                                                  \
    const uint32_t base = sbase + (buf) * STAGE_B;                             \
    CPA16(base + e0b,              a0p + ko);                                  \
    CPA16(base + e1b,              a1p + ko);                                  \
    CPA16(base + TILE_B + e0b,     a0p + ko + 1024);                           \
    CPA16(base + TILE_B + e1b,     a1p + ko + 1024);                           \
    CPA16(base + 2*TILE_B + e0b,   b0p + ko);                                  \
    CPA16(base + 2*TILE_B + e1b,   b1p + ko);                                  \
    CPA16(base + 3*TILE_B + e0b,   b0p + ko + 1024);                           \
    CPA16(base + 3*TILE_B + e1b,   b1p + ko + 1024);                           \
    asm volatile("cp.async.commit_group;");                                    \
} while (0)

    ISSUE3(0, 0);
    ISSUE3(1, 1);

    float acc[4][4][4];
#pragma unroll
    for (int mi = 0; mi < 4; mi++)
#pragma unroll
        for (int ni = 0; ni < 4; ni++)
#pragma unroll
            for (int r = 0; r < 4; r++) acc[mi][ni][r] = 0.f;

    const int arow  = wm * 64 + (lane & 15);
    const int acol8 = (lane >> 4) * 8;
    const int brow  = (lane & 7) + ((lane & 16) ? 8 : 0);
    const int bcol8 = (lane & 8) ? 8 : 0;

    for (int c = 0; c < NCHUNK; c++) {
        const int buf = c & 1;
        if (c + 1 < NCHUNK) asm volatile("cp.async.wait_group 1;");
        else                asm volatile("cp.async.wait_group 0;");
        __syncthreads();

        const __nv_bfloat16* sAh = sm3 + buf * STAGE_E;
        const __nv_bfloat16* sAl = sAh + TILE_E;
        const __nv_bfloat16* sBh = sAh + 2 * TILE_E;
        const __nv_bfloat16* sBl = sAh + 3 * TILE_E;

#pragma unroll
        for (int kk = 0; kk < 2; kk++) {
            uint32_t ah[4][4], al[4][4], bh[2][4];
#pragma unroll
            for (int mi = 0; mi < 4; mi++) {
                uint32_t addr = smem_u32(&sAh[(arow + mi * 16) * RS + kk * 16 + acol8]);
                LDSM4(ah[mi][0], ah[mi][1], ah[mi][2], ah[mi][3], addr);
            }
#pragma unroll
            for (int mi = 0; mi < 4; mi++) {
                uint32_t addr = smem_u32(&sAl[(arow + mi * 16) * RS + kk * 16 + acol8]);
                LDSM4(al[mi][0], al[mi][1], al[mi][2], al[mi][3], addr);
            }
#pragma unroll
            for (int np = 0; np < 2; np++) {
                uint32_t addr = smem_u32(&sBh[(wn * 32 + np * 16 + brow) * RS
                                              + kk * 16 + bcol8]);
                LDSM4(bh[np][0], bh[np][1], bh[np][2], bh[np][3], addr);
            }
#pragma unroll
            for (int mi = 0; mi < 4; mi++)
#pragma unroll
                for (int np = 0; np < 2; np++) {
                    MMA16816(acc[mi][2*np],   ah[mi][0], ah[mi][1], ah[mi][2], ah[mi][3],
                             bh[np][0], bh[np][1]);
                    MMA16816(acc[mi][2*np+1], ah[mi][0], ah[mi][1], ah[mi][2], ah[mi][3],
                             bh[np][2], bh[np][3]);
                }
#pragma unroll
            for (int mi = 0; mi < 4; mi++)
#pragma unroll
                for (int np = 0; np < 2; np++) {
                    MMA16816(acc[mi][2*np],   al[mi][0], al[mi][1], al[mi][2], al[mi][3],
                             bh[np][0], bh[np][1]);
                    MMA16816(acc[mi][2*np+1], al[mi][0], al[mi][1], al[mi][2], al[mi][3],
                             bh[np][2], bh[np][3]);
                }
#pragma unroll
            for (int np = 0; np < 2; np++) {
                uint32_t bl[4];
                uint32_t addr = smem_u32(&sBl[(wn * 32 + np * 16 + brow) * RS
                                              + kk * 16 + bcol8]);
                LDSM4(bl[0], bl[1], bl[2], bl[3], addr);
#pragma unroll
                for (int mi = 0; mi < 4; mi++) {
                    MMA16816(acc[mi][2*np],   ah[mi][0], ah[mi][1], ah[mi][2], ah[mi][3],
                             bl[0], bl[1]);
                    MMA16816(acc[mi][2*np+1], ah[mi][0], ah[mi][1], ah[mi][2], ah[mi][3],
                             bl[2], bl[3]);
                }
            }
        }

        __syncthreads();
        if (c + 2 < NCHUNK) ISSUE3(buf, c + 2);
    }

    // QKV epilogue: fp16. Q -> hi/lo pair; K -> single; V -> single transposed.
    const int gid = lane >> 2;
    const int tig = lane & 3;
#pragma unroll
    for (int mi = 0; mi < 4; mi++) {
        const int m0 = bm + wm * 64 + mi * 16 + gid;
#pragma unroll
        for (int ni = 0; ni < 4; ni++) {
            const int n0 = bn + wn * 32 + ni * 8 + tig * 2;
            const int which = n0 >> 10;
            const int rem = n0 & 1023;
            const int h = rem >> 6;
            const int d = rem & 63;
#pragma unroll
            for (int half = 0; half < 2; half++) {
                const int m = m0 + half * 8;
                const int b = m >> 11;
                const int t = m & 2047;
                const size_t bh_ = (size_t)(b * HH + h);
                float v0 = acc[mi][ni][2 * half];
                float v1 = acc[mi][ni][2 * half + 1];
                if (which == 2) {
                    const size_t base = bh_ * DKK * TT + (size_t)t;
                    g_vt16[base + (size_t)d * TT]       = __float2half_rn(v0);
                    g_vt16[base + (size_t)(d + 1) * TT] = __float2half_rn(v1);
                } else if (which == 1) {
                    const size_t off = bh_ * TT * DKK + (size_t)t * DKK + d;
                    *(uint32_t*)(g_k16 + off) = pack_f16(v0, v1);
                } else {
                    const size_t off = bh_ * TT * DKK + (size_t)t * DKK + d;
                    uint32_t hi2 = pack_f16(v0, v1);
                    float lo0 = v0 - f16lo_f(hi2);
                    float lo1 = v1 - f16hi_f(hi2);
                    *(uint32_t*)(g_q16h + off) = hi2;
                    *(uint32_t*)(g_q16l + off) = pack_f16(lo0, lo1);
                }
            }
        }
    }
}

// ---------------------------------------------------------------------------
// fp16 2-term GEMM NT (proj): C = [Oh|Ol] * [Wh|Wh]^T = O * Wh^T, fp32 out.
// ---------------------------------------------------------------------------
#define NCHF (K2 / 32)    // 64

__global__ __launch_bounds__(256) void hgemm2_f16(const __half* __restrict__ A,
                                                  const __half* __restrict__ Bw,
                                                  float* __restrict__ Cout)
{
    __shared__ __align__(16) __half sA[2][128 * RS];
    __shared__ __align__(16) __half sB[2][128 * RS];

    const int tid  = threadIdx.x;
    const int lane = tid & 31;
    const int warp = tid >> 5;
    const int wm   = warp & 1;
    const int wn   = warp >> 1;
    const int bm   = blockIdx.y * 128;
    const int bn   = blockIdx.x * 128;

    const int r0 = tid >> 2, o0 = tid & 3;
    const int r1 = (tid + 256) >> 2, o1 = (tid + 256) & 3;

    const __half* Ag = A  + (size_t)bm * K2;
    const __half* Bg = Bw + (size_t)bn * K2;

    uint32_t sa0[2], sa1[2], sb0[2], sb1[2];
#pragma unroll
    for (int s = 0; s < 2; s++) {
        sa0[s] = smem_u32(&sA[s][r0 * RS + o0 * 8]);
        sa1[s] = smem_u32(&sA[s][r1 * RS + o1 * 8]);
        sb0[s] = smem_u32(&sB[s][r0 * RS + o0 * 8]);
        sb1[s] = smem_u32(&sB[s][r1 * RS + o1 * 8]);
    }

#define ISSUE_F(buf, ch) do {                                                  \
    const __half* ap0 = Ag + (size_t)r0 * K2 + (ch) * 32 + o0 * 8;             \
    const __half* ap1 = Ag + (size_t)r1 * K2 + (ch) * 32 + o1 * 8;             \
    const __half* bp0 = Bg + (size_t)r0 * K2 + (ch) * 32 + o0 * 8;             \
    const __half* bp1 = Bg + (size_t)r1 * K2 + (ch) * 32 + o1 * 8;             \
    CPA16(sa0[buf], ap0); CPA16(sa1[buf], ap1);                                \
    CPA16(sb0[buf], bp0); CPA16(sb1[buf], bp1);                                \
    asm volatile("cp.async.commit_group;");                                    \
} while (0)

    ISSUE_F(0, 0);
    ISSUE_F(1, 1);

    float acc[4][4][4];
#pragma unroll
    for (int mi = 0; mi < 4; mi++)
#pragma unroll
        for (int ni = 0; ni < 4; ni++)
#pragma unroll
            for (int r = 0; r < 4; r++) acc[mi][ni][r] = 0.f;

    const int l16 = lane & 15;

    for (int c = 0; c < NCHF; c++) {
        const int buf = c & 1;
        if (c + 1 < NCHF) asm volatile("cp.async.wait_group 1;");
        else              asm volatile("cp.async.wait_group 0;");
        __syncthreads();

        const __half* sAb = sA[buf];
        const __half* sBb = sB[buf];

#pragma unroll
        for (int kk = 0; kk < 2; kk++) {
            uint32_t af[4][4];
            uint32_t bf[4][2];
#pragma unroll
            for (int mi = 0; mi < 4; mi++) {
                uint32_t addr = smem_u32(&sAb[(wm * 64 + mi * 16 + (lane & 15)) * RS
                                              + kk * 16 + (lane >> 4) * 8]);
                LDSM4(af[mi][0], af[mi][1], af[mi][2], af[mi][3], addr);
            }
#pragma unroll
            for (int ni = 0; ni < 4; ni++) {
                uint32_t addr = smem_u32(&sBb[(wn * 32 + ni * 8 + (l16 & 7)) * RS
                                              + kk * 16 + (l16 >> 3) * 8]);
                LDSM2(bf[ni][0], bf[ni][1], addr);
            }
#pragma unroll
            for (int mi = 0; mi < 4; mi++)
#pragma unroll
                for (int ni = 0; ni < 4; ni++)
                    MMA16816H(acc[mi][ni], af[mi][0], af[mi][1], af[mi][2], af[mi][3],
                              bf[ni][0], bf[ni][1]);
        }

        __syncthreads();
        if (c + 2 < NCHF) ISSUE_F(buf, c + 2);
    }

    const int gid = lane >> 2;
    const int tig = lane & 3;
#pragma unroll
    for (int mi = 0; mi < 4; mi++) {
        const int m0 = bm + wm * 64 + mi * 16 + gid;
#pragma unroll
        for (int ni = 0; ni < 4; ni++) {
            const int n0 = bn + wn * 32 + ni * 8 + tig * 2;
            *(float2*)(Cout + (size_t)m0 * 1024 + n0) =
                make_float2(acc[mi][ni][0], acc[mi][ni][1]);
            *(float2*)(Cout + (size_t)(m0 + 8) * 1024 + n0) =
                make_float2(acc[mi][ni][2], acc[mi][ni][3]);
        }
    }
}

// ---------------------------------------------------------------------------
// fp16 flash attention, causal. S = [Qh|Ql]*Kh (2 passes), O = [Ph|Pl]*Vh.
// KV stage = Kh + Vh only (16 KB). Epilogue -> g_att16 [Oh|Ol].
// ---------------------------------------------------------------------------
#define QTILE 128
#define KTILE 64
#define ARS 72
#define QELEMS (QTILE * ARS)
#define KTELEMS (KTILE * ARS)
#define STG0 (2 * QELEMS)
#define STG_STRIDE (2 * KTELEMS)
#define ATT_SMEM_B ((STG0 + 2 * STG_STRIDE) * 2)   // 73728 bytes

__global__ __launch_bounds__(256) void attn_mma()
{
    extern __shared__ __align__(16) __half smh[];

    const int tid  = threadIdx.x;
    const int lane = tid & 31;
    const int w    = tid >> 5;
    const int qt   = gridDim.x - 1 - blockIdx.x;
    const int h    = blockIdx.y;
    const int b    = blockIdx.z;
    const int q0   = qt * QTILE;
    const size_t bh = (size_t)(b * HH + h);
    const int njt  = 2 * qt + 2;

    const __half* Qh = g_q16h + bh * TT * DKK;
    const __half* Ql = g_q16l + bh * TT * DKK;
    const __half* Kh = g_k16  + bh * TT * DKK;
    const __half* Vh = g_vt16 + bh * DKK * TT;

    // Q tile (hi + lo): 2048 chunks of 16B
#pragma unroll
    for (int i = 0; i < 8; i++) {
        int lin = tid + i * 256;
        int arr = lin >> 10;
        int r   = (lin & 1023) >> 3;
        int ch  = lin & 7;
        const __half* src = (arr ? Ql : Qh) + (size_t)(q0 + r) * DKK + ch * 8;
        uint32_t dst = smem_u32(&smh[arr * QELEMS + r * ARS + ch * 8]);
        CPA16(dst, src);
    }

    const int lr = tid >> 3, lch = tid & 7;
#define ISSUE_KV(jt, s) do {                                                      \
    int k0_ = (jt) * KTILE;                                                       \
    __half* base = smh + STG0 + (s) * STG_STRIDE;                                 \
    CPA16(smem_u32(&base[lr * ARS + lch * 8]),                                    \
          Kh + (size_t)(k0_ + lr) * DKK + lch * 8);                               \
    CPA16(smem_u32(&base[(lr + 32) * ARS + lch * 8]),                             \
          Kh + (size_t)(k0_ + lr + 32) * DKK + lch * 8);                          \
    CPA16(smem_u32(&base[KTELEMS + lr * ARS + lch * 8]),                          \
          Vh + (size_t)lr * TT + k0_ + lch * 8);                                  \
    CPA16(smem_u32(&base[KTELEMS + (lr + 32) * ARS + lch * 8]),                   \
          Vh + (size_t)(lr + 32) * TT + k0_ + lch * 8);                           \
    asm volatile("cp.async.commit_group;");                                       \
} while (0)

    ISSUE_KV(0, 0);
    ISSUE_KV(1, 1);

    float oacc[8][4];
#pragma unroll
    for (int ni = 0; ni < 8; ni++)
#pragma unroll
        for (int r = 0; r < 4; r++) oacc[ni][r] = 0.f;
    float mrow[2] = {-1e30f, -1e30f};
    float lrow[2] = {0.f, 0.f};

    uint32_t ah[4][4];
    bool ah_loaded = false;

    const int arow = w * 16 + (lane & 15);
    const int acol8 = (lane >> 4) * 8;
    const int brow = (lane & 7) + ((lane & 16) ? 8 : 0);
    const int bcol8 = (lane & 8) ? 8 : 0;
    const int rr = lane >> 2;
    const int cc2 = (lane & 3) * 2;

    for (int jt = 0; jt < njt; jt++) {
        const int s = jt & 1;
        if (jt + 1 < njt) asm volatile("cp.async.wait_group 1;");
        else              asm volatile("cp.async.wait_group 0;");
        __syncthreads();

        __half* sKh = smh + STG0 + s * STG_STRIDE;
        __half* sVh = sKh + KTELEMS;

        if (!ah_loaded) {
            ah_loaded = true;
#pragma unroll
            for (int kk = 0; kk < 4; kk++) {
                uint32_t addr = smem_u32(&smh[arow * ARS + kk * 16 + acol8]);
                LDSM4(ah[kk][0], ah[kk][1], ah[kk][2], ah[kk][3], addr);
            }
        }

        float sacc[8][4];
#pragma unroll
        for (int ni = 0; ni < 8; ni++)
#pragma unroll
            for (int r = 0; r < 4; r++) sacc[ni][r] = 0.f;

#pragma unroll
        for (int kk = 0; kk < 4; kk++) {
            uint32_t al4[4];
            {
                uint32_t addr = smem_u32(&smh[QELEMS + arow * ARS + kk * 16 + acol8]);
                LDSM4(al4[0], al4[1], al4[2], al4[3], addr);
            }
            uint32_t bh4[4][4];
#pragma unroll
            for (int np = 0; np < 4; np++) {
                uint32_t addr = smem_u32(&sKh[(np * 16 + brow) * ARS + kk * 16 + bcol8]);
                LDSM4(bh4[np][0], bh4[np][1], bh4[np][2], bh4[np][3], addr);
            }
            // pass 1: Qh * Kh
#pragma unroll
            for (int np = 0; np < 4; np++) {
                MMA16816H(sacc[2*np],   ah[kk][0], ah[kk][1], ah[kk][2], ah[kk][3],
                          bh4[np][0], bh4[np][1]);
                MMA16816H(sacc[2*np+1], ah[kk][0], ah[kk][1], ah[kk][2], ah[kk][3],
                          bh4[np][2], bh4[np][3]);
            }
            // pass 2: Ql * Kh
#pragma unroll
            for (int np = 0; np < 4; np++) {
                MMA16816H(sacc[2*np],   al4[0], al4[1], al4[2], al4[3],
                          bh4[np][0], bh4[np][1]);
                MMA16816H(sacc[2*np+1], al4[0], al4[1], al4[2], al4[3],
                          bh4[np][2], bh4[np][3]);
            }
        }

        const int k0 = jt * KTILE;
        const int r0 = q0 + w * 16 + rr;
        const int r1 = r0 + 8;
        const bool need_mask = (k0 + KTILE - 1 > r0);
#pragma unroll
        for (int ni = 0; ni < 8; ni++) {
            const int col = k0 + ni * 8 + cc2;
#pragma unroll
            for (int c = 0; c < 2; c++) {
                sacc[ni][c]     *= 0.125f;
                sacc[ni][2 + c] *= 0.125f;
                if (need_mask) {
                    if (col + c > r0) sacc[ni][c]     = -1e30f;
                    if (col + c > r1) sacc[ni][2 + c] = -1e30f;
                }
            }
        }

        float mx0 = -1e30f, mx1 = -1e30f;
#pragma unroll
        for (int ni = 0; ni < 8; ni++) {
            mx0 = fmaxf(mx0, fmaxf(sacc[ni][0], sacc[ni][1]));
            mx1 = fmaxf(mx1, fmaxf(sacc[ni][2], sacc[ni][3]));
        }
        mx0 = fmaxf(mx0, __shfl_xor_sync(0xffffffffu, mx0, 1));
        mx0 = fmaxf(mx0, __shfl_xor_sync(0xffffffffu, mx0, 2));
        mx1 = fmaxf(mx1, __shfl_xor_sync(0xffffffffu, mx1, 1));
        mx1 = fmaxf(mx1, __shfl_xor_sync(0xffffffffu, mx1, 2));
        const float mn0 = fmaxf(mrow[0], mx0);
        const float mn1 = fmaxf(mrow[1], mx1);
        const float al0 = __expf(mrow[0] - mn0);
        const float al1 = __expf(mrow[1] - mn1);
        mrow[0] = mn0; mrow[1] = mn1;
        float sum0 = 0.f, sum1 = 0.f;
#pragma unroll
        for (int ni = 0; ni < 8; ni++) {
            sacc[ni][0] = __expf(sacc[ni][0] - mn0); sum0 += sacc[ni][0];
            sacc[ni][1] = __expf(sacc[ni][1] - mn0); sum0 += sacc[ni][1];
            sacc[ni][2] = __expf(sacc[ni][2] - mn1); sum1 += sacc[ni][2];
            sacc[ni][3] = __expf(sacc[ni][3] - mn1); sum1 += sacc[ni][3];
        }
        sum0 += __shfl_xor_sync(0xffffffffu, sum0, 1);
        sum0 += __shfl_xor_sync(0xffffffffu, sum0, 2);
        sum1 += __shfl_xor_sync(0xffffffffu, sum1, 1);
        sum1 += __shfl_xor_sync(0xffffffffu, sum1, 2);
        lrow[0] = lrow[0] * al0 + sum0;
        lrow[1] = lrow[1] * al1 + sum1;
#pragma unroll
        for (int ni = 0; ni < 8; ni++) {
            oacc[ni][0] *= al0; oacc[ni][1] *= al0;
            oacc[ni][2] *= al1; oacc[ni][3] *= al1;
        }

        // O += P V (fp16 2-term: exact P split, V single)
#pragma unroll
        for (int kk = 0; kk < 4; kk++) {
            const int b2 = 2 * kk, b3 = 2 * kk + 1;
            uint32_t pah[4], pal[4];
            pah[0] = pack_f16(sacc[b2][0], sacc[b2][1]);
            pah[1] = pack_f16(sacc[b2][2], sacc[b2][3]);
            pah[2] = pack_f16(sacc[b3][0], sacc[b3][1]);
            pah[3] = pack_f16(sacc[b3][2], sacc[b3][3]);
            pal[0] = pack_f16(sacc[b2][0] - f16lo_f(pah[0]), sacc[b2][1] - f16hi_f(pah[0]));
            pal[1] = pack_f16(sacc[b2][2] - f16lo_f(pah[1]), sacc[b2][3] - f16hi_f(pah[1]));
            pal[2] = pack_f16(sacc[b3][0] - f16lo_f(pah[2]), sacc[b3][1] - f16hi_f(pah[2]));
            pal[3] = pack_f16(sacc[b3][2] - f16lo_f(pah[3]), sacc[b3][3] - f16hi_f(pah[3]));
            uint32_t vh4[4][4];
#pragma unroll
            for (int dp = 0; dp < 4; dp++) {
                uint32_t addr = smem_u32(&sVh[(dp * 16 + brow) * ARS + kk * 16 + bcol8]);
                LDSM4(vh4[dp][0], vh4[dp][1], vh4[dp][2], vh4[dp][3], addr);
            }
            // pass 1: Ph * Vh
#pragma unroll
            for (int dp = 0; dp < 4; dp++) {
                MMA16816H(oacc[2*dp],   pah[0], pah[1], pah[2], pah[3],
                          vh4[dp][0], vh4[dp][1]);
                MMA16816H(oacc[2*dp+1], pah[0], pah[1], pah[2], pah[3],
                          vh4[dp][2], vh4[dp][3]);
            }
            // pass 2: Pl * Vh
#pragma unroll
            for (int dp = 0; dp < 4; dp++) {
                MMA16816H(oacc[2*dp],   pal[0], pal[1], pal[2], pal[3],
                          vh4[dp][0], vh4[dp][1]);
                MMA16816H(oacc[2*dp+1], pal[0], pal[1], pal[2], pal[3],
                          vh4[dp][2], vh4[dp][3]);
            }
        }

        __syncthreads();
        if (jt + 2 < njt) ISSUE_KV(jt + 2, s);
    }

    // epilogue: normalize, fp16 hi/lo split, write g_att16 [Oh | Ol]
    const float inv0 = 1.f / lrow[0];
    const float inv1 = 1.f / lrow[1];
    const int row0 = q0 + w * 16 + rr;
    const size_t m0 = (size_t)b * TT + row0;
    __half* dst0 = g_att16 + m0 * K2 + h * 64;
    __half* dst1 = g_att16 + (m0 + 8) * K2 + h * 64;
#pragma unroll
    for (int ni = 0; ni < 8; ni++) {
        const int d = ni * 8 + cc2;
        float v0 = oacc[ni][0] * inv0, v1 = oacc[ni][1] * inv0;
        float v2 = oacc[ni][2] * inv1, v3 = oacc[ni][3] * inv1;
        uint32_t h0 = pack_f16(v0, v1);
        uint32_t l0 = pack_f16(v0 - f16lo_f(h0), v1 - f16hi_f(h0));
        uint32_t h1 = pack_f16(v2, v3);
        uint32_t l1 = pack_f16(v2 - f16lo_f(h1), v3 - f16hi_f(h1));
        *(uint32_t*)(dst0 + d)        = h0;
        *(uint32_t*)(dst0 + 1024 + d) = l0;
        *(uint32_t*)(dst1 + d)        = h1;
        *(uint32_t*)(dst1 + 1024 + d) = l1;
    }
}

// ---------------------------------------------------------------------------
extern "C" void kernel_launch(void* const* d_in, const int* in_sizes, int n_in,
                              void* d_out, int out_size)
{
    const float* x      = (const float*)d_in[0];   // [2, 2048, 1024]
    const float* w_attn = (const float*)d_in[1];   // [3072, 1024]
    const float* w_proj = (const float*)d_in[2];   // [1024, 1024]
    float* out = (float*)d_out;                    // [2, 2048, 1024]

    cudaFuncSetAttribute(hgemm3_nt,
                         cudaFuncAttributeMaxDynamicSharedMemorySize, GSMEM_B);
    cudaFuncSetAttribute(attn_mma,
                         cudaFuncAttributeMaxDynamicSharedMemorySize, ATT_SMEM_B);

    void *xs, *was, *att16, *wp16;
    cudaGetSymbolAddress(&xs,    g_xs);
    cudaGetSymbolAddress(&was,   g_was);
    cudaGetSymbolAddress(&att16, g_att16);
    cudaGetSymbolAddress(&wp16,  g_wp16);

    // 0) splits: bf16 [hi|lo] for x, w_attn; fp16 [Wh|Wh] for w_proj
    split_kernel<<<(BB*TT*CC/4 + 255)/256, 256>>>(x,      (__nv_bfloat16*)xs,  BB*TT*CC);
    split_kernel<<<(3*CC*CC/4  + 255)/256, 256>>>(w_attn, (__nv_bfloat16*)was, 3*CC*CC);
    split_w16<<<(CC*CC/4 + 255)/256, 256>>>(w_proj, (__half*)wp16, CC*CC);

    // 1) QKV projection (3-term bf16 GEMM) -> fp16 Q(hi/lo), K, V^T
    {
        dim3 grid(3 * CC / 128, (BB * TT) / 128);  // (24, 32)
        hgemm3_nt<<<grid, 256, GSMEM_B>>>((const __nv_bfloat16*)xs,
                                          (const __nv_bfloat16*)was);
    }

    // 2) fp16 causal flash attention -> g_att16 [Oh|Ol]
    {
        dim3 grid(TT / QTILE, HH, BB);             // (16, 16, 2)
        attn_mma<<<grid, 256, ATT_SMEM_B>>>();
    }

    // 3) output projection: fp16 2-term GEMM (O * Wh^T)
    {
        dim3 grid(CC / 128, (BB * TT) / 128);      // (8, 32)
        hgemm2_f16<<<grid, 256>>>((const __half*)att16, (const __half*)wp16, out);
    }
}